// round 4
// baseline (speedup 1.0000x reference)
#include <cuda_runtime.h>
#include <math.h>

// Problem constants (deterministic per setup_inputs)
#define HD   1024
#define SEQ  1024
#define LO   256
#define LDOC 768
#define NBAT 32
#define NBZ  8
#define NL   4

// ---------------- device scratch ----------------
__device__ float g_S   [96 * LO * LO];
__device__ float g_kq  [NBAT * LO * LDOC];
__device__ float g_att [96 * LO * HD];
__device__ float g_gate[NBAT * LO * HD];
__device__ float g_corr[NBAT * LO * HD];
__device__ float g_opt [NBAT * LO * HD];
__device__ float g_a   [NBAT * LO * HD];
__device__ float g_co  [NBAT * LO * HD];
__device__ float g_fus [NBAT * LO * HD];
__device__ float g_sa  [NBAT * LO * HD];
__device__ float g_cow [NBAT * LO * LO];
__device__ float g_kl  [96 * LO];
__device__ float g_ql  [NBAT * LO];

struct ZOffs { long long o[12]; };

// ---------------- helpers ----------------
__device__ __forceinline__ float to_tf32(float x) {
    unsigned u;
    asm("cvt.rna.tf32.f32 %0, %1;" : "=r"(u) : "f"(x));
    return __uint_as_float(u);
}

__device__ __forceinline__ float blockReduceMax(float v, float* sm) {
    #pragma unroll
    for (int o = 16; o; o >>= 1) v = fmaxf(v, __shfl_xor_sync(0xffffffffu, v, o));
    int w = threadIdx.x >> 5;
    if ((threadIdx.x & 31) == 0) sm[w] = v;
    __syncthreads();
    if (threadIdx.x < 32) {
        v = (threadIdx.x < (blockDim.x >> 5)) ? sm[threadIdx.x] : -3.4e38f;
        #pragma unroll
        for (int o = 4; o; o >>= 1) v = fmaxf(v, __shfl_xor_sync(0xffffffffu, v, o));
        if (threadIdx.x == 0) sm[0] = v;
    }
    __syncthreads();
    v = sm[0];
    __syncthreads();
    return v;
}

__device__ __forceinline__ float blockReduceSum(float v, float* sm) {
    #pragma unroll
    for (int o = 16; o; o >>= 1) v += __shfl_xor_sync(0xffffffffu, v, o);
    int w = threadIdx.x >> 5;
    if ((threadIdx.x & 31) == 0) sm[w] = v;
    __syncthreads();
    if (threadIdx.x < 32) {
        v = (threadIdx.x < (blockDim.x >> 5)) ? sm[threadIdx.x] : 0.0f;
        #pragma unroll
        for (int o = 4; o; o >>= 1) v += __shfl_xor_sync(0xffffffffu, v, o);
        if (threadIdx.x == 0) sm[0] = v;
    }
    __syncthreads();
    v = sm[0];
    __syncthreads();
    return v;
}

// ---------------- TF32 tensor-core GEMM: 128 threads, 2x2 warps, 64x64 warp tile ----
#define BM 128
#define BN 128
#define BKT 16
#define NTHR 128

template <int TRANS_B, int HASA2>
__global__ __launch_bounds__(NTHR, 2)
void tgemm_kernel(int K,
                  const float* __restrict__ A, int lda, long long sA0, ZOffs aoffs,
                  const float* __restrict__ A2, long long sA20, ZOffs a2offs, int amode,
                  const float* __restrict__ B, int ldb, long long sB0, ZOffs boffs,
                  float* __restrict__ C, int ldc, long long sC0, ZOffs coffs,
                  int nz0,
                  const float* __restrict__ ascale,
                  const float* __restrict__ bias,
                  int accumulate, int act)
{
    constexpr int ASTR  = BKT + 4;   // 20
    constexpr int BSTR0 = BN + 8;    // 136
    constexpr int ASZ   = BM * ASTR;
    constexpr int BSZ   = TRANS_B ? (BN * ASTR) : (BKT * BSTR0);

    __shared__ float As[2][ASZ];
    __shared__ float Bs[2][BSZ];

    const int z  = blockIdx.z;
    const int z1 = z / nz0;
    const int z0 = z - z1 * nz0;
    const float* Ab  = A + aoffs.o[z1] + (long long)z0 * sA0;
    const float* A2b = HASA2 ? (A2 + a2offs.o[z1] + (long long)z0 * sA20) : nullptr;
    const float* Bb  = B + boffs.o[z1] + (long long)z0 * sB0;
    float*       Cb  = C + coffs.o[z1] + (long long)z0 * sC0;

    const int bm = blockIdx.y * BM;
    const int bn = blockIdx.x * BN;
    const int tid  = threadIdx.x;
    const int lane = tid & 31;
    const int warp = tid >> 5;        // 0..3
    const int warpM = warp >> 1;      // 0..1
    const int warpN = warp & 1;       // 0..1
    const int g = lane >> 2;          // 0..7
    const int c = lane & 3;           // 0..3

    // loaders (128 threads): A row = tid, 4 float4 covering k0..k0+15
    const int nnrow = tid >> 5;       // 0..3 (NN B loader)
    const int nncol = (tid & 31) * 4; // 0..124

    float4 ar[4], br[4];

    float cfr[4][8][4];
    #pragma unroll
    for (int mt = 0; mt < 4; ++mt)
        #pragma unroll
        for (int nt = 0; nt < 8; ++nt)
            #pragma unroll
            for (int r = 0; r < 4; ++r) cfr[mt][nt][r] = 0.0f;

    auto ldg_stage = [&](int k0) {
        const float* arow = Ab + (long long)(bm + tid) * lda + k0;
        #pragma unroll
        for (int i = 0; i < 4; ++i) ar[i] = *reinterpret_cast<const float4*>(arow + i * 4);
        if (HASA2) {
            const float* a2row = A2b + (long long)(bm + tid) * lda + k0;
            #pragma unroll
            for (int i = 0; i < 4; ++i) {
                float4 x = *reinterpret_cast<const float4*>(a2row + i * 4);
                if (amode == 1) { ar[i].x *= x.x; ar[i].y *= x.y; ar[i].z *= x.z; ar[i].w *= x.w; }
                else           { ar[i].x -= x.x; ar[i].y -= x.y; ar[i].z -= x.z; ar[i].w -= x.w; }
            }
        }
        if (ascale) {
            #pragma unroll
            for (int i = 0; i < 4; ++i) {
                ar[i].x *= ascale[k0 + i * 4 + 0];
                ar[i].y *= ascale[k0 + i * 4 + 1];
                ar[i].z *= ascale[k0 + i * 4 + 2];
                ar[i].w *= ascale[k0 + i * 4 + 3];
            }
        }
        if (TRANS_B) {
            const float* brow = Bb + (long long)(bn + tid) * ldb + k0;
            #pragma unroll
            for (int i = 0; i < 4; ++i) br[i] = *reinterpret_cast<const float4*>(brow + i * 4);
        } else {
            #pragma unroll
            for (int i = 0; i < 4; ++i)
                br[i] = *reinterpret_cast<const float4*>(Bb + (long long)(k0 + nnrow + 4 * i) * ldb + bn + nncol);
        }
    };

    auto sts_stage = [&](int buf) {
        #pragma unroll
        for (int i = 0; i < 4; ++i) {
            float4 t;
            t.x = to_tf32(ar[i].x); t.y = to_tf32(ar[i].y); t.z = to_tf32(ar[i].z); t.w = to_tf32(ar[i].w);
            *reinterpret_cast<float4*>(&As[buf][tid * ASTR + i * 4]) = t;
        }
        if (TRANS_B) {
            #pragma unroll
            for (int i = 0; i < 4; ++i) {
                float4 t;
                t.x = to_tf32(br[i].x); t.y = to_tf32(br[i].y); t.z = to_tf32(br[i].z); t.w = to_tf32(br[i].w);
                *reinterpret_cast<float4*>(&Bs[buf][tid * ASTR + i * 4]) = t;
            }
        } else {
            #pragma unroll
            for (int i = 0; i < 4; ++i) {
                float4 t;
                t.x = to_tf32(br[i].x); t.y = to_tf32(br[i].y); t.z = to_tf32(br[i].z); t.w = to_tf32(br[i].w);
                *reinterpret_cast<float4*>(&Bs[buf][(nnrow + 4 * i) * BSTR0 + nncol]) = t;
            }
        }
    };

    auto compute_stage = [&](int buf) {
        const unsigned* Au = reinterpret_cast<const unsigned*>(As[buf]);
        const unsigned* Bu = reinterpret_cast<const unsigned*>(Bs[buf]);
        #pragma unroll
        for (int kk = 0; kk < 2; ++kk) {
            unsigned af[4][4], bf[8][2];
            #pragma unroll
            for (int mt = 0; mt < 4; ++mt) {
                const int r0 = (warpM * 64 + mt * 16 + g) * ASTR + kk * 8 + c;
                af[mt][0] = Au[r0];
                af[mt][1] = Au[r0 + 8 * ASTR];
                af[mt][2] = Au[r0 + 4];
                af[mt][3] = Au[r0 + 8 * ASTR + 4];
            }
            #pragma unroll
            for (int nt = 0; nt < 8; ++nt) {
                const int n0 = warpN * 64 + nt * 8 + g;
                if (TRANS_B) {
                    bf[nt][0] = Bu[n0 * ASTR + kk * 8 + c];
                    bf[nt][1] = Bu[n0 * ASTR + kk * 8 + c + 4];
                } else {
                    bf[nt][0] = Bu[(kk * 8 + c)     * BSTR0 + n0];
                    bf[nt][1] = Bu[(kk * 8 + c + 4) * BSTR0 + n0];
                }
            }
            #pragma unroll
            for (int mt = 0; mt < 4; ++mt)
                #pragma unroll
                for (int nt = 0; nt < 8; ++nt) {
                    asm volatile(
                        "mma.sync.aligned.m16n8k8.row.col.f32.tf32.tf32.f32 "
                        "{%0,%1,%2,%3}, {%4,%5,%6,%7}, {%8,%9}, {%0,%1,%2,%3};"
                        : "+f"(cfr[mt][nt][0]), "+f"(cfr[mt][nt][1]),
                          "+f"(cfr[mt][nt][2]), "+f"(cfr[mt][nt][3])
                        : "r"(af[mt][0]), "r"(af[mt][1]), "r"(af[mt][2]), "r"(af[mt][3]),
                          "r"(bf[nt][0]), "r"(bf[nt][1]));
                }
        }
    };

    int buf = 0;
    ldg_stage(0);
    sts_stage(0);
    __syncthreads();
    for (int k0 = BKT; k0 < K; k0 += BKT) {
        ldg_stage(k0);
        compute_stage(buf);
        sts_stage(buf ^ 1);
        __syncthreads();
        buf ^= 1;
    }
    compute_stage(buf);

    #pragma unroll
    for (int mt = 0; mt < 4; ++mt) {
        const int row = bm + warpM * 64 + mt * 16 + g;
        #pragma unroll
        for (int nt = 0; nt < 8; ++nt) {
            const int col = bn + warpN * 64 + nt * 8 + c * 2;
            #pragma unroll
            for (int half = 0; half < 2; ++half) {
                float* p = Cb + (long long)(row + half * 8) * ldc + col;
                float v0 = cfr[mt][nt][half * 2 + 0];
                float v1 = cfr[mt][nt][half * 2 + 1];
                if (accumulate) { v0 += p[0]; v1 += p[1]; }
                if (bias) { v0 += bias[col]; v1 += bias[col + 1]; }
                if (act == 1)      { v0 = fmaxf(v0, 0.0f); v1 = fmaxf(v1, 0.0f); }
                else if (act == 2) { v0 = tanhf(v0); v1 = tanhf(v1); }
                else if (act == 3) { v0 = 1.0f / (1.0f + expf(-v0)); v1 = 1.0f / (1.0f + expf(-v1)); }
                p[0] = v0; p[1] = v1;
            }
        }
    }
}

// ---------------- batched rowdot ----------------
__global__ void rowdot_kernel(const float* __restrict__ X, ZOffs offs, int nz0, long long s0,
                              int ld, const float* __restrict__ w, float* __restrict__ out,
                              int rows, int Kd)
{
    __shared__ float sm[32];
    const int r = blockIdx.x, z = blockIdx.y;
    const int z1 = z / nz0, z0 = z - z1 * nz0;
    const float* x = X + offs.o[z1] + (long long)z0 * s0 + (long long)r * ld;
    float s = 0.0f;
    for (int k = threadIdx.x; k < Kd; k += 256) s += x[k] * w[k];
    s = blockReduceSum(s, sm);
    if (threadIdx.x == 0) out[(long long)z * rows + r] = s;
}

// ---------------- row softmax in-place ----------------
__global__ void softmax_row_kernel(float* __restrict__ S, int ldS, long long strideS,
                                   const float* __restrict__ kl, int Lk)
{
    __shared__ float sm[32];
    const int q = blockIdx.x, z = blockIdx.y;
    float* row = S + (long long)z * strideS + (long long)q * ldS;
    const float* klb = kl + (long long)z * Lk;

    float v[3];
    int n = 0;
    float m = -3.4e38f;
    for (int k = threadIdx.x; k < Lk; k += 256) {
        float x = row[k] + klb[k];
        v[n++] = x;
        m = fmaxf(m, x);
    }
    m = blockReduceMax(m, sm);
    float s = 0.0f;
    for (int t = 0; t < n; ++t) { v[t] = expf(v[t] - m); s += v[t]; }
    s = blockReduceSum(s, sm);
    const float inv = 1.0f / s;
    n = 0;
    for (int k = threadIdx.x; k < Lk; k += 256) row[k] = v[n++] * inv;
}

// ---------------- column softmax (doc stage) ----------------
__global__ void softmax_col_kernel(const float* __restrict__ S, float* __restrict__ kq,
                                   const float* __restrict__ ql)
{
    const int x = threadIdx.x & 31;
    const int y = threadIdx.x >> 5;
    const int col = blockIdx.x * 32 + x;
    const int z = blockIdx.y;
    const float* Sb = S + (long long)z * (LO * LDOC);
    const float* qlb = ql + (long long)z * LO;

    float vals[LO / 8];
    float m = -3.4e38f;
    #pragma unroll 4
    for (int it = 0; it < LO / 8; ++it) {
        const int r = it * 8 + y;
        float v = qlb[r] + Sb[(long long)r * LDOC + col];
        vals[it] = v;
        m = fmaxf(m, v);
    }
    __shared__ float red[8][32];
    red[y][x] = m;
    __syncthreads();
    if (y == 0) {
        float mm = red[0][x];
        #pragma unroll
        for (int t = 1; t < 8; ++t) mm = fmaxf(mm, red[t][x]);
        red[0][x] = mm;
    }
    __syncthreads();
    m = red[0][x];
    __syncthreads();

    float s = 0.0f;
    #pragma unroll 4
    for (int it = 0; it < LO / 8; ++it) { vals[it] = expf(vals[it] - m); s += vals[it]; }
    red[y][x] = s;
    __syncthreads();
    if (y == 0) {
        float ss = 0.0f;
        #pragma unroll
        for (int t = 0; t < 8; ++t) ss += red[t][x];
        red[0][x] = ss;
    }
    __syncthreads();
    const float inv = 1.0f / red[0][x];

    float* kqb = kq + (long long)z * (LO * LDOC);
    #pragma unroll 4
    for (int it = 0; it < LO / 8; ++it)
        kqb[(long long)(it * 8 + y) * LDOC + col] = vals[it] * inv;
}

// ---------------- gate combine ----------------
__global__ void gate_combine_kernel(float* __restrict__ opt,
                                    const float* __restrict__ enc, long long sE,
                                    const float* __restrict__ corr,
                                    const float* __restrict__ gate, int nPer)
{
    const int z = blockIdx.y;
    const int t = blockIdx.x * 256 + threadIdx.x;
    const float g = gate[(long long)z * nPer + t];
    const float e = enc[(long long)z * sE + t];
    const float c = corr[(long long)z * nPer + t];
    opt[(long long)z * nPer + t] = e * g + c * (1.0f - g);
}

// ---------------- final max over positions ----------------
__global__ void maxreduce_kernel(const float* __restrict__ f, float* __restrict__ out)
{
    const int h = blockIdx.x * 256 + threadIdx.x;
    const int b = blockIdx.y;
    float m = -3.4e38f;
    const float* base = f + (long long)b * LO * HD + h;
    #pragma unroll 8
    for (int r = 0; r < LO; ++r) m = fmaxf(m, base[(long long)r * HD]);
    out[(long long)b * HD + h] = m;
}

// ---------------- host orchestration ----------------
static ZOffs zzero() { ZOffs z; for (int i = 0; i < 12; ++i) z.o[i] = 0; return z; }

struct GemmArgs {
    const float* A; int lda; long long sA0; ZOffs aoffs;
    const float* A2; long long sA20; ZOffs a2offs; int amode;
    const float* B; int ldb; long long sB0; ZOffs boffs;
    float* C; int ldc; long long sC0; ZOffs coffs;
    int nz0;
    const float* ascale; const float* bias; int acc; int act;
};

static void launch_gemm(int transB, int M, int N, int K, int nz, const GemmArgs& a)
{
    dim3 grid(N / BN, M / BM, nz);
    const bool hasA2 = (a.A2 != nullptr);
    if (transB) {
        if (hasA2)
            tgemm_kernel<1, 1><<<grid, NTHR>>>(K, a.A, a.lda, a.sA0, a.aoffs, a.A2, a.sA20, a.a2offs, a.amode,
                                               a.B, a.ldb, a.sB0, a.boffs, a.C, a.ldc, a.sC0, a.coffs,
                                               a.nz0, a.ascale, a.bias, a.acc, a.act);
        else
            tgemm_kernel<1, 0><<<grid, NTHR>>>(K, a.A, a.lda, a.sA0, a.aoffs, a.A2, a.sA20, a.a2offs, a.amode,
                                               a.B, a.ldb, a.sB0, a.boffs, a.C, a.ldc, a.sC0, a.coffs,
                                               a.nz0, a.ascale, a.bias, a.acc, a.act);
    } else {
        if (hasA2)
            tgemm_kernel<0, 1><<<grid, NTHR>>>(K, a.A, a.lda, a.sA0, a.aoffs, a.A2, a.sA20, a.a2offs, a.amode,
                                               a.B, a.ldb, a.sB0, a.boffs, a.C, a.ldc, a.sC0, a.coffs,
                                               a.nz0, a.ascale, a.bias, a.acc, a.act);
        else
            tgemm_kernel<0, 0><<<grid, NTHR>>>(K, a.A, a.lda, a.sA0, a.aoffs, a.A2, a.sA20, a.a2offs, a.amode,
                                               a.B, a.ldb, a.sB0, a.boffs, a.C, a.ldc, a.sC0, a.coffs,
                                               a.nz0, a.ascale, a.bias, a.acc, a.act);
    }
}

extern "C" void kernel_launch(void* const* d_in, const int* in_sizes, int n_in,
                              void* d_out, int out_size)
{
    const float* last   = (const float*)d_in[4];
    const float* ow2    = (const float*)d_in[6];
    const float* ow3    = (const float*)d_in[7];
    const float* dw1    = (const float*)d_in[8];
    const float* dw2    = (const float*)d_in[9];
    const float* dw3    = (const float*)d_in[10];
    const float* sw2    = (const float*)d_in[12];
    const float* sw3    = (const float*)d_in[13];
    const float* comp_w = (const float*)d_in[14];
    const float* comp_b = (const float*)d_in[15];
    const float* gate_w = (const float*)d_in[16];
    const float* gate_b = (const float*)d_in[17];
    const float* attn_w = (const float*)d_in[18];
    const float* attn_b = (const float*)d_in[19];
    const float* self_w = (const float*)d_in[20];
    const float* self_b = (const float*)d_in[21];

    float *S_, *kq_, *att_, *gate_, *corr_, *opt_, *a_, *co_, *fus_, *sa_, *cow_, *kl_, *ql_;
    cudaGetSymbolAddress((void**)&S_,   g_S);
    cudaGetSymbolAddress((void**)&kq_,  g_kq);
    cudaGetSymbolAddress((void**)&att_, g_att);
    cudaGetSymbolAddress((void**)&gate_,g_gate);
    cudaGetSymbolAddress((void**)&corr_,g_corr);
    cudaGetSymbolAddress((void**)&opt_, g_opt);
    cudaGetSymbolAddress((void**)&a_,   g_a);
    cudaGetSymbolAddress((void**)&co_,  g_co);
    cudaGetSymbolAddress((void**)&fus_, g_fus);
    cudaGetSymbolAddress((void**)&sa_,  g_sa);
    cudaGetSymbolAddress((void**)&cow_, g_cow);
    cudaGetSymbolAddress((void**)&kl_,  g_kl);
    cudaGetSymbolAddress((void**)&ql_,  g_ql);

    const long long sSeq = (long long)SEQ * HD;
    const long long sQ   = 4LL * SEQ * HD;
    const long long LoH  = (long long)LO * HD;
    const int nPer = LO * HD;

    long long curoff[NL], kvoff[12], attoff[12];
    for (int i = 0; i < NL; ++i) curoff[i] = ((long long)i * SEQ + LDOC) * HD;
    for (int i = 0, p = 0; i < NL; ++i)
        for (int j = 0; j < NL; ++j) {
            if (j == i) continue;
            kvoff[p] = ((long long)j * SEQ + LDOC) * HD;
            attoff[p] = (long long)p * NBZ * LoH;
            ++p;
        }

    GemmArgs ga;

    // ===== Stage A: all 12 pair attentions =====
    {
        ZOffs kvo = zzero();
        for (int p = 0; p < 12; ++p) kvo.o[p] = kvoff[p];
        rowdot_kernel<<<dim3(LO, 96), 256>>>(last, kvo, NBZ, sQ, HD, ow2, kl_, LO, HD);

        ga = {};
        ga.A = last; ga.lda = HD; ga.sA0 = sQ;
        for (int p = 0; p < 12; ++p) ga.aoffs.o[p] = curoff[p / 3];
        ga.B = last; ga.ldb = HD; ga.sB0 = sQ; ga.boffs = kvo;
        ga.C = S_; ga.ldc = LO; ga.sC0 = (long long)LO * LO;
        for (int p = 0; p < 12; ++p) ga.coffs.o[p] = (long long)p * NBZ * LO * LO;
        ga.nz0 = NBZ; ga.ascale = ow3;
        launch_gemm(1, LO, LO, HD, 96, ga);

        softmax_row_kernel<<<dim3(LO, 96), 256>>>(S_, LO, (long long)LO * LO, kl_, LO);

        ga = {};
        ga.A = S_; ga.lda = LO; ga.sA0 = (long long)LO * LO;
        for (int p = 0; p < 12; ++p) ga.aoffs.o[p] = (long long)p * NBZ * LO * LO;
        ga.B = last; ga.ldb = HD; ga.sB0 = sQ; ga.boffs = kvo;
        ga.C = att_; ga.ldc = HD; ga.sC0 = LoH;
        for (int p = 0; p < 12; ++p) ga.coffs.o[p] = attoff[p];
        ga.nz0 = NBZ;
        launch_gemm(0, LO, HD, LO, 96, ga);
    }

    // ===== comp: 7 segments batched over all 4 labels =====
    {
        ZOffs curo = zzero(), corro = zzero();
        for (int i = 0; i < NL; ++i) { curo.o[i] = curoff[i]; corro.o[i] = (long long)i * LoH; }

        ga = {};
        ga.A = last; ga.lda = HD; ga.sA0 = sQ; ga.aoffs = curo;
        ga.B = comp_w; ga.ldb = 7 * HD; ga.sB0 = 0; ga.boffs = zzero();
        ga.C = corr_; ga.ldc = HD; ga.sC0 = 4 * LoH; ga.coffs = corro;
        ga.nz0 = NBZ;
        launch_gemm(1, LO, HD, HD, 32, ga);

        for (int m = 0; m < 3; ++m) {
            ZOffs atto = zzero();
            for (int i = 0; i < NL; ++i) atto.o[i] = attoff[i * 3 + m];
            ga = {};
            ga.A = last; ga.lda = HD; ga.sA0 = sQ; ga.aoffs = curo;
            ga.A2 = att_; ga.sA20 = LoH; ga.a2offs = atto; ga.amode = 1;
            ga.B = comp_w + (1 + 2 * m) * HD; ga.ldb = 7 * HD; ga.sB0 = 0; ga.boffs = zzero();
            ga.C = corr_; ga.ldc = HD; ga.sC0 = 4 * LoH; ga.coffs = corro;
            ga.nz0 = NBZ; ga.acc = 1;
            launch_gemm(1, LO, HD, HD, 32, ga);
            ga.A2 = att_; ga.amode = 2;
            ga.B = comp_w + (2 + 2 * m) * HD;
            if (m == 2) { ga.bias = comp_b; ga.act = 2; }
            launch_gemm(1, LO, HD, HD, 32, ga);
        }
    }

    // ===== Stage B: gate + option =====
    {
        ga = {};
        ga.A = last; ga.lda = HD; ga.sA0 = sSeq; ga.aoffs = zzero(); ga.aoffs.o[0] = (long long)LDOC * HD;
        ga.B = gate_w; ga.ldb = 2 * HD; ga.sB0 = 0; ga.boffs = zzero();
        ga.C = gate_; ga.ldc = HD; ga.sC0 = LoH; ga.coffs = zzero();
        ga.nz0 = NBAT;
        launch_gemm(1, LO, HD, HD, 32, ga);

        ga.A = corr_; ga.sA0 = LoH; ga.aoffs = zzero();
        ga.B = gate_w + HD;
        ga.acc = 1; ga.bias = gate_b; ga.act = 3;
        launch_gemm(1, LO, HD, HD, 32, ga);

        gate_combine_kernel<<<dim3(nPer / 256, NBAT), 256>>>(opt_, last + (long long)LDOC * HD, sSeq, corr_, gate_, nPer);
    }

    // ===== Stage C: doc attention =====
    {
        ZOffs z0o = zzero();
        rowdot_kernel<<<dim3(LO, NBAT), 256>>>(opt_, z0o, NBAT, LoH, HD, dw1, ql_, LO, HD);
        rowdot_kernel<<<dim3(LDOC, NBAT), 256>>>(last, z0o, NBAT, sSeq, HD, dw2, kl_, LDOC, HD);

        ga = {};
        ga.A = opt_; ga.lda = HD; ga.sA0 = LoH; ga.aoffs = zzero();
        ga.B = last; ga.ldb = HD; ga.sB0 = sSeq; ga.boffs = zzero();
        ga.C = S_; ga.ldc = LDOC; ga.sC0 = (long long)LO * LDOC; ga.coffs = zzero();
        ga.nz0 = NBAT; ga.ascale = dw3;
        launch_gemm(1, LO, LDOC, HD, 32, ga);

        softmax_col_kernel<<<dim3(LDOC / 32, NBAT), 256>>>(S_, kq_, ql_);
        softmax_row_kernel<<<dim3(LO, NBAT), 256>>>(S_, LDOC, (long long)LO * LDOC, kl_, LDOC);

        ga = {};
        ga.A = S_; ga.lda = LDOC; ga.sA0 = (long long)LO * LDOC; ga.aoffs = zzero();
        ga.B = last; ga.ldb = HD; ga.sB0 = sSeq; ga.boffs = zzero();
        ga.C = a_; ga.ldc = HD; ga.sC0 = LoH; ga.coffs = zzero();
        ga.nz0 = NBAT;
        launch_gemm(0, LO, HD, LDOC, 32, ga);

        ga = {};
        ga.A = S_; ga.lda = LDOC; ga.sA0 = (long long)LO * LDOC; ga.aoffs = zzero();
        ga.B = kq_; ga.ldb = LDOC; ga.sB0 = (long long)LO * LDOC; ga.boffs = zzero();
        ga.C = cow_; ga.ldc = LO; ga.sC0 = (long long)LO * LO; ga.coffs = zzero();
        ga.nz0 = NBAT;
        launch_gemm(1, LO, LO, LDOC, 32, ga);

        ga = {};
        ga.A = cow_; ga.lda = LO; ga.sA0 = (long long)LO * LO; ga.aoffs = zzero();
        ga.B = opt_; ga.ldb = HD; ga.sB0 = LoH; ga.boffs = zzero();
        ga.C = co_; ga.ldc = HD; ga.sC0 = LoH; ga.coffs = zzero();
        ga.nz0 = NBAT;
        launch_gemm(0, LO, HD, LO, 32, ga);
    }

    // ===== Stage D: fusion =====
    {
        const float* srcs[3] = {opt_, a_, co_};
        for (int s = 0; s < 3; ++s) {
            ga = {};
            ga.A = srcs[s]; ga.lda = HD; ga.sA0 = LoH; ga.aoffs = zzero();
            ga.B = attn_w + s * HD; ga.ldb = 3 * HD; ga.sB0 = 0; ga.boffs = zzero();
            ga.C = fus_; ga.ldc = HD; ga.sC0 = LoH; ga.coffs = zzero();
            ga.nz0 = NBAT; ga.acc = (s > 0);
            if (s == 2) { ga.bias = attn_b; ga.act = 1; }
            launch_gemm(1, LO, HD, HD, 32, ga);
        }
    }

    // ===== Stage E: self attention =====
    {
        ZOffs z0o = zzero();
        rowdot_kernel<<<dim3(LO, NBAT), 256>>>(fus_, z0o, NBAT, LoH, HD, sw2, kl_, LO, HD);

        ga = {};
        ga.A = fus_; ga.lda = HD; ga.sA0 = LoH; ga.aoffs = zzero();
        ga.B = fus_; ga.ldb = HD; ga.sB0 = LoH; ga.boffs = zzero();
        ga.C = S_; ga.ldc = LO; ga.sC0 = (long long)LO * LO; ga.coffs = zzero();
        ga.nz0 = NBAT; ga.ascale = sw3;
        launch_gemm(1, LO, LO, HD, 32, ga);

        softmax_row_kernel<<<dim3(LO, NBAT), 256>>>(S_, LO, (long long)LO * LO, kl_, LO);

        ga = {};
        ga.A = S_; ga.lda = LO; ga.sA0 = (long long)LO * LO; ga.aoffs = zzero();
        ga.B = fus_; ga.ldb = HD; ga.sB0 = LoH; ga.boffs = zzero();
        ga.C = sa_; ga.ldc = HD; ga.sC0 = LoH; ga.coffs = zzero();
        ga.nz0 = NBAT;
        launch_gemm(0, LO, HD, LO, 32, ga);
    }

    // ===== Stage F: fusion2 =====
    {
        ga = {};
        ga.A = fus_; ga.lda = HD; ga.sA0 = LoH; ga.aoffs = zzero();
        ga.B = self_w; ga.ldb = 4 * HD; ga.sB0 = 0; ga.boffs = zzero();
        ga.C = corr_; ga.ldc = HD; ga.sC0 = LoH; ga.coffs = zzero();
        ga.nz0 = NBAT;
        launch_gemm(1, LO, HD, HD, 32, ga);
        ga.A = sa_; ga.B = self_w + HD; ga.acc = 1;
        launch_gemm(1, LO, HD, HD, 32, ga);
        ga.A = fus_; ga.A2 = sa_; ga.sA20 = LoH; ga.a2offs = zzero(); ga.amode = 1;
        ga.B = self_w + 2 * HD;
        launch_gemm(1, LO, HD, HD, 32, ga);
        ga.amode = 2; ga.B = self_w + 3 * HD; ga.bias = self_b; ga.act = 1;
        launch_gemm(1, LO, HD, HD, 32, ga);
    }

    // ===== Stage G: max over positions =====
    maxreduce_kernel<<<dim3(HD / 256, NBAT), 256>>>(corr_, (float*)d_out);
}

// round 6
// speedup vs baseline: 1.6579x; 1.6579x over previous
#include <cuda_runtime.h>
#include <math.h>
#include <stdint.h>

#define HD   1024
#define SEQ  1024
#define LO   256
#define LDOC 768
#define NBAT 32
#define NBZ  8
#define NL   4

// ---------------- device scratch ----------------
__device__ float g_S   [96 * LO * LO];
__device__ float g_kq  [NBAT * LO * LDOC];
__device__ float g_att [96 * LO * HD];
__device__ float g_corr[NBAT * LO * HD];
__device__ float g_opt [NBAT * LO * HD];
__device__ float g_a   [NBAT * LO * HD];
__device__ float g_co  [NBAT * LO * HD];
__device__ float g_fus [NBAT * LO * HD];
__device__ float g_sa  [NBAT * LO * HD];
__device__ float g_cow [NBAT * LO * LO];
__device__ float g_kl  [96 * LO];
__device__ float g_ql  [NBAT * LO];

struct ZOffs { long long o[12]; };

struct Seg {
    const float* A;
    const float* A2;
    long long c0, c1, s0;     // A offset = c0 + c1*z1 + s0*z0
    long long ac0, ac1, as0;  // A2 offset affine
    int amode;                // 0 none, 1 mul, 2 sub
    int pad;
};
struct SegArgs { Seg segs[8]; int nseg; };

// ---------------- helpers ----------------
__device__ __forceinline__ float to_tf32(float x) {
    unsigned u;
    asm("cvt.rna.tf32.f32 %0, %1;" : "=r"(u) : "f"(x));
    return __uint_as_float(u);
}

__device__ __forceinline__ float blockReduceMax(float v, float* sm) {
    #pragma unroll
    for (int o = 16; o; o >>= 1) v = fmaxf(v, __shfl_xor_sync(0xffffffffu, v, o));
    int w = threadIdx.x >> 5;
    if ((threadIdx.x & 31) == 0) sm[w] = v;
    __syncthreads();
    if (threadIdx.x < 32) {
        v = (threadIdx.x < (blockDim.x >> 5)) ? sm[threadIdx.x] : -3.4e38f;
        #pragma unroll
        for (int o = 4; o; o >>= 1) v = fmaxf(v, __shfl_xor_sync(0xffffffffu, v, o));
        if (threadIdx.x == 0) sm[0] = v;
    }
    __syncthreads();
    v = sm[0];
    __syncthreads();
    return v;
}

__device__ __forceinline__ float blockReduceSum(float v, float* sm) {
    #pragma unroll
    for (int o = 16; o; o >>= 1) v += __shfl_xor_sync(0xffffffffu, v, o);
    int w = threadIdx.x >> 5;
    if ((threadIdx.x & 31) == 0) sm[w] = v;
    __syncthreads();
    if (threadIdx.x < 32) {
        v = (threadIdx.x < (blockDim.x >> 5)) ? sm[threadIdx.x] : 0.0f;
        #pragma unroll
        for (int o = 4; o; o >>= 1) v += __shfl_xor_sync(0xffffffffu, v, o);
        if (threadIdx.x == 0) sm[0] = v;
    }
    __syncthreads();
    v = sm[0];
    __syncthreads();
    return v;
}

#define BM 128
#define BN 128
#define BKT 16
#define ASTR (BKT + 4)
#define BSTR0 (BN + 8)

// ======== fragment compute (shared by NT kernels): 8 warps 2x4, 64x32 warp tile =====
#define NT_COMPUTE_STAGE(Au, Bu)                                                     \
    _Pragma("unroll")                                                                \
    for (int kk = 0; kk < 2; ++kk) {                                                 \
        unsigned af[4][4], bf[4][2];                                                 \
        _Pragma("unroll")                                                            \
        for (int mt = 0; mt < 4; ++mt) {                                             \
            const int r0 = (warpM * 64 + mt * 16 + g) * ASTR + kk * 8 + c;           \
            af[mt][0] = Au[r0];                                                      \
            af[mt][1] = Au[r0 + 8 * ASTR];                                           \
            af[mt][2] = Au[r0 + 4];                                                  \
            af[mt][3] = Au[r0 + 8 * ASTR + 4];                                       \
        }                                                                            \
        _Pragma("unroll")                                                            \
        for (int nt = 0; nt < 4; ++nt) {                                             \
            const int n0 = warpN * 32 + nt * 8 + g;                                  \
            bf[nt][0] = Bu[n0 * ASTR + kk * 8 + c];                                  \
            bf[nt][1] = Bu[n0 * ASTR + kk * 8 + c + 4];                              \
        }                                                                            \
        _Pragma("unroll")                                                            \
        for (int mt = 0; mt < 4; ++mt)                                               \
            _Pragma("unroll")                                                        \
            for (int nt = 0; nt < 4; ++nt) {                                         \
                asm volatile(                                                        \
                    "mma.sync.aligned.m16n8k8.row.col.f32.tf32.tf32.f32 "            \
                    "{%0,%1,%2,%3}, {%4,%5,%6,%7}, {%8,%9}, {%0,%1,%2,%3};"          \
                    : "+f"(cfr[mt][nt][0]), "+f"(cfr[mt][nt][1]),                    \
                      "+f"(cfr[mt][nt][2]), "+f"(cfr[mt][nt][3])                     \
                    : "r"(af[mt][0]), "r"(af[mt][1]), "r"(af[mt][2]), "r"(af[mt][3]),\
                      "r"(bf[nt][0]), "r"(bf[nt][1]));                               \
            }                                                                        \
    }

// ================= plain NT GEMM (stage A/C/E S-matrices, cow): C = A @ B^T =========
__global__ __launch_bounds__(256, 2)
void tgemm_kernel(int K,
                  const float* __restrict__ A, int lda, long long sA0, ZOffs aoffs,
                  const float* __restrict__ B, int ldb, long long sB0, ZOffs boffs,
                  float* __restrict__ C, int ldc, long long sC0, ZOffs coffs,
                  int nz0, const float* __restrict__ ascale)
{
    __shared__ float As[2][BM * ASTR];
    __shared__ float Bs[2][BN * ASTR];

    const int z  = blockIdx.z;
    const int z1 = z / nz0;
    const int z0 = z - z1 * nz0;
    const float* Ab = A + aoffs.o[z1] + (long long)z0 * sA0;
    const float* Bb = B + boffs.o[z1] + (long long)z0 * sB0;
    float*       Cb = C + coffs.o[z1] + (long long)z0 * sC0;

    const int bm = blockIdx.y * BM;
    const int bn = blockIdx.x * BN;
    const int tid  = threadIdx.x;
    const int lane = tid & 31;
    const int warp = tid >> 5;
    const int warpM = warp >> 2;
    const int warpN = warp & 3;
    const int g = lane >> 2;
    const int c = lane & 3;

    const int arow = tid >> 2;      // 0..63
    const int ac4  = tid & 3;

    float4 ar0, ar1, br0, br1;

    float cfr[4][4][4];
    #pragma unroll
    for (int mt = 0; mt < 4; ++mt)
        #pragma unroll
        for (int nt = 0; nt < 4; ++nt)
            #pragma unroll
            for (int r = 0; r < 4; ++r) cfr[mt][nt][r] = 0.0f;

    auto ldg_stage = [&](int k0) {
        ar0 = *reinterpret_cast<const float4*>(Ab + (long long)(bm + arow)      * lda + k0 + ac4 * 4);
        ar1 = *reinterpret_cast<const float4*>(Ab + (long long)(bm + arow + 64) * lda + k0 + ac4 * 4);
        if (ascale) {
            const float s0 = ascale[k0 + ac4 * 4 + 0];
            const float s1 = ascale[k0 + ac4 * 4 + 1];
            const float s2 = ascale[k0 + ac4 * 4 + 2];
            const float s3 = ascale[k0 + ac4 * 4 + 3];
            ar0.x *= s0; ar0.y *= s1; ar0.z *= s2; ar0.w *= s3;
            ar1.x *= s0; ar1.y *= s1; ar1.z *= s2; ar1.w *= s3;
        }
        br0 = *reinterpret_cast<const float4*>(Bb + (long long)(bn + arow)      * ldb + k0 + ac4 * 4);
        br1 = *reinterpret_cast<const float4*>(Bb + (long long)(bn + arow + 64) * ldb + k0 + ac4 * 4);
    };

    auto sts_stage = [&](int buf) {
        float4 t;
        t.x = to_tf32(ar0.x); t.y = to_tf32(ar0.y); t.z = to_tf32(ar0.z); t.w = to_tf32(ar0.w);
        *reinterpret_cast<float4*>(&As[buf][arow * ASTR + ac4 * 4]) = t;
        t.x = to_tf32(ar1.x); t.y = to_tf32(ar1.y); t.z = to_tf32(ar1.z); t.w = to_tf32(ar1.w);
        *reinterpret_cast<float4*>(&As[buf][(arow + 64) * ASTR + ac4 * 4]) = t;
        t.x = to_tf32(br0.x); t.y = to_tf32(br0.y); t.z = to_tf32(br0.z); t.w = to_tf32(br0.w);
        *reinterpret_cast<float4*>(&Bs[buf][arow * ASTR + ac4 * 4]) = t;
        t.x = to_tf32(br1.x); t.y = to_tf32(br1.y); t.z = to_tf32(br1.z); t.w = to_tf32(br1.w);
        *reinterpret_cast<float4*>(&Bs[buf][(arow + 64) * ASTR + ac4 * 4]) = t;
    };

    int buf = 0;
    ldg_stage(0);
    sts_stage(0);
    __syncthreads();
    for (int k0 = BKT; k0 < K; k0 += BKT) {
        ldg_stage(k0);
        {
            const unsigned* Au = reinterpret_cast<const unsigned*>(As[buf]);
            const unsigned* Bu = reinterpret_cast<const unsigned*>(Bs[buf]);
            NT_COMPUTE_STAGE(Au, Bu)
        }
        sts_stage(buf ^ 1);
        __syncthreads();
        buf ^= 1;
    }
    {
        const unsigned* Au = reinterpret_cast<const unsigned*>(As[buf]);
        const unsigned* Bu = reinterpret_cast<const unsigned*>(Bs[buf]);
        NT_COMPUTE_STAGE(Au, Bu)
    }

    #pragma unroll
    for (int mt = 0; mt < 4; ++mt) {
        const int row = bm + warpM * 64 + mt * 16 + g;
        #pragma unroll
        for (int nt = 0; nt < 4; ++nt) {
            const int col = bn + warpN * 32 + nt * 8 + c * 2;
            #pragma unroll
            for (int half = 0; half < 2; ++half) {
                float* p = Cb + (long long)(row + half * 8) * ldc + col;
                p[0] = cfr[mt][nt][half * 2 + 0];
                p[1] = cfr[mt][nt][half * 2 + 1];
            }
        }
    }
}

// ================= segmented-K NT GEMM (concat in K, fused epilogue) ================
// A per 1024-wide k-segment; lda fixed = 1024. B row-major [N, Ktot], ldb = Ktot.
// act: 0 none, 1 relu, 2 tanh, 4 gate: out = e1*sig(v) + e2*(1-sig(v))
__global__ __launch_bounds__(256, 2)
void segk_kernel(int Ktot, SegArgs sga,
                 const float* __restrict__ B, int ldb,
                 float* __restrict__ C, int ldc, long long sC0, ZOffs coffs, int nz0,
                 const float* __restrict__ bias, int act,
                 const float* __restrict__ e1, long long e1s,
                 const float* __restrict__ e2, long long e2s)
{
    __shared__ float As[2][BM * ASTR];
    __shared__ float Bs[2][BN * ASTR];

    const int z  = blockIdx.z;
    const int z1 = z / nz0;
    const int z0 = z - z1 * nz0;
    float* Cb = C + coffs.o[z1] + (long long)z0 * sC0;

    const int bm = blockIdx.y * BM;
    const int bn = blockIdx.x * BN;
    const int tid  = threadIdx.x;
    const int lane = tid & 31;
    const int warp = tid >> 5;
    const int warpM = warp >> 2;
    const int warpN = warp & 3;
    const int g = lane >> 2;
    const int c = lane & 3;

    const int arow = tid >> 2;
    const int ac4  = tid & 3;

    int curseg = -1;
    const float* Ab = nullptr;
    const float* A2b = nullptr;
    int am = 0;

    float4 ar0, ar1, br0, br1;

    float cfr[4][4][4];
    #pragma unroll
    for (int mt = 0; mt < 4; ++mt)
        #pragma unroll
        for (int nt = 0; nt < 4; ++nt)
            #pragma unroll
            for (int r = 0; r < 4; ++r) cfr[mt][nt][r] = 0.0f;

    auto ldg_stage = [&](int k0) {
        const int s = k0 >> 10;
        if (s != curseg) {
            curseg = s;
            const Seg& sg = sga.segs[s];
            Ab = sg.A + sg.c0 + sg.c1 * z1 + sg.s0 * z0;
            am = sg.amode;
            A2b = am ? (sg.A2 + sg.ac0 + sg.ac1 * z1 + sg.as0 * z0) : nullptr;
        }
        const int kl = (k0 & 1023) + ac4 * 4;
        ar0 = *reinterpret_cast<const float4*>(Ab + (long long)(bm + arow)      * 1024 + kl);
        ar1 = *reinterpret_cast<const float4*>(Ab + (long long)(bm + arow + 64) * 1024 + kl);
        if (am) {
            float4 x0 = *reinterpret_cast<const float4*>(A2b + (long long)(bm + arow)      * 1024 + kl);
            float4 x1 = *reinterpret_cast<const float4*>(A2b + (long long)(bm + arow + 64) * 1024 + kl);
            if (am == 1) {
                ar0.x *= x0.x; ar0.y *= x0.y; ar0.z *= x0.z; ar0.w *= x0.w;
                ar1.x *= x1.x; ar1.y *= x1.y; ar1.z *= x1.z; ar1.w *= x1.w;
            } else {
                ar0.x -= x0.x; ar0.y -= x0.y; ar0.z -= x0.z; ar0.w -= x0.w;
                ar1.x -= x1.x; ar1.y -= x1.y; ar1.z -= x1.z; ar1.w -= x1.w;
            }
        }
        br0 = *reinterpret_cast<const float4*>(B + (long long)(bn + arow)      * ldb + k0 + ac4 * 4);
        br1 = *reinterpret_cast<const float4*>(B + (long long)(bn + arow + 64) * ldb + k0 + ac4 * 4);
    };

    auto sts_stage = [&](int buf) {
        float4 t;
        t.x = to_tf32(ar0.x); t.y = to_tf32(ar0.y); t.z = to_tf32(ar0.z); t.w = to_tf32(ar0.w);
        *reinterpret_cast<float4*>(&As[buf][arow * ASTR + ac4 * 4]) = t;
        t.x = to_tf32(ar1.x); t.y = to_tf32(ar1.y); t.z = to_tf32(ar1.z); t.w = to_tf32(ar1.w);
        *reinterpret_cast<float4*>(&As[buf][(arow + 64) * ASTR + ac4 * 4]) = t;
        t.x = to_tf32(br0.x); t.y = to_tf32(br0.y); t.z = to_tf32(br0.z); t.w = to_tf32(br0.w);
        *reinterpret_cast<float4*>(&Bs[buf][arow * ASTR + ac4 * 4]) = t;
        t.x = to_tf32(br1.x); t.y = to_tf32(br1.y); t.z = to_tf32(br1.z); t.w = to_tf32(br1.w);
        *reinterpret_cast<float4*>(&Bs[buf][(arow + 64) * ASTR + ac4 * 4]) = t;
    };

    int buf = 0;
    ldg_stage(0);
    sts_stage(0);
    __syncthreads();
    for (int k0 = BKT; k0 < Ktot; k0 += BKT) {
        ldg_stage(k0);
        {
            const unsigned* Au = reinterpret_cast<const unsigned*>(As[buf]);
            const unsigned* Bu = reinterpret_cast<const unsigned*>(Bs[buf]);
            NT_COMPUTE_STAGE(Au, Bu)
        }
        sts_stage(buf ^ 1);
        __syncthreads();
        buf ^= 1;
    }
    {
        const unsigned* Au = reinterpret_cast<const unsigned*>(As[buf]);
        const unsigned* Bu = reinterpret_cast<const unsigned*>(Bs[buf]);
        NT_COMPUTE_STAGE(Au, Bu)
    }

    #pragma unroll
    for (int mt = 0; mt < 4; ++mt) {
        const int row = bm + warpM * 64 + mt * 16 + g;
        #pragma unroll
        for (int nt = 0; nt < 4; ++nt) {
            const int col = bn + warpN * 32 + nt * 8 + c * 2;
            #pragma unroll
            for (int half = 0; half < 2; ++half) {
                const int r2 = row + half * 8;
                float* p = Cb + (long long)r2 * ldc + col;
                float v0 = cfr[mt][nt][half * 2 + 0];
                float v1 = cfr[mt][nt][half * 2 + 1];
                if (bias) { v0 += bias[col]; v1 += bias[col + 1]; }
                if (act == 1)      { v0 = fmaxf(v0, 0.0f); v1 = fmaxf(v1, 0.0f); }
                else if (act == 2) { v0 = tanhf(v0); v1 = tanhf(v1); }
                else if (act == 4) {
                    const float g0 = 1.0f / (1.0f + expf(-v0));
                    const float g1 = 1.0f / (1.0f + expf(-v1));
                    const float* pe = e1 + (long long)z0 * e1s + (long long)r2 * ldc + col;
                    const float* pc = e2 + (long long)z0 * e2s + (long long)r2 * ldc + col;
                    v0 = pe[0] * g0 + pc[0] * (1.0f - g0);
                    v1 = pe[1] * g1 + pc[1] * (1.0f - g1);
                }
                p[0] = v0; p[1] = v1;
            }
        }
    }
}

// ================= mma.sync NN GEMM (P@V etc.) =================
__global__ __launch_bounds__(256, 2)
void nngemm_kernel(int K,
                   const float* __restrict__ A, int lda, long long sA0, ZOffs aoffs,
                   const float* __restrict__ B, int ldb, long long sB0, ZOffs boffs,
                   float* __restrict__ C, int ldc, long long sC0, ZOffs coffs,
                   int nz0)
{
    __shared__ float As[2][BM * ASTR];
    __shared__ float Bs[2][BKT * BSTR0];

    const int z  = blockIdx.z;
    const int z1 = z / nz0;
    const int z0 = z - z1 * nz0;
    const float* Ab = A + aoffs.o[z1] + (long long)z0 * sA0;
    const float* Bb = B + boffs.o[z1] + (long long)z0 * sB0;
    float*       Cb = C + coffs.o[z1] + (long long)z0 * sC0;

    const int bm = blockIdx.y * BM;
    const int bn = blockIdx.x * BN;
    const int tid  = threadIdx.x;
    const int lane = tid & 31;
    const int warp = tid >> 5;
    const int warpM = warp >> 2;
    const int warpN = warp & 3;
    const int g = lane >> 2;
    const int c = lane & 3;

    const int arow = tid >> 2;
    const int ac4  = tid & 3;
    const int brow = tid >> 5;
    const int bcol = (tid & 31) * 4;

    float4 ar0, ar1, br0, br1;

    float cfr[4][4][4];
    #pragma unroll
    for (int mt = 0; mt < 4; ++mt)
        #pragma unroll
        for (int nt = 0; nt < 4; ++nt)
            #pragma unroll
            for (int r = 0; r < 4; ++r) cfr[mt][nt][r] = 0.0f;

    auto ldg_stage = [&](int k0) {
        ar0 = *reinterpret_cast<const float4*>(Ab + (long long)(bm + arow)      * lda + k0 + ac4 * 4);
        ar1 = *reinterpret_cast<const float4*>(Ab + (long long)(bm + arow + 64) * lda + k0 + ac4 * 4);
        br0 = *reinterpret_cast<const float4*>(Bb + (long long)(k0 + brow)     * ldb + bn + bcol);
        br1 = *reinterpret_cast<const float4*>(Bb + (long long)(k0 + brow + 8) * ldb + bn + bcol);
    };

    auto sts_stage = [&](int buf) {
        float4 t;
        t.x = to_tf32(ar0.x); t.y = to_tf32(ar0.y); t.z = to_tf32(ar0.z); t.w = to_tf32(ar0.w);
        *reinterpret_cast<float4*>(&As[buf][arow * ASTR + ac4 * 4]) = t;
        t.x = to_tf32(ar1.x); t.y = to_tf32(ar1.y); t.z = to_tf32(ar1.z); t.w = to_tf32(ar1.w);
        *reinterpret_cast<float4*>(&As[buf][(arow + 64) * ASTR + ac4 * 4]) = t;
        t.x = to_tf32(br0.x); t.y = to_tf32(br0.y); t.z = to_tf32(br0.z); t.w = to_tf32(br0.w);
        *reinterpret_cast<float4*>(&Bs[buf][brow * BSTR0 + bcol]) = t;
        t.x = to_tf32(br1.x); t.y = to_tf32(br1.y); t.z = to_tf32(br1.z); t.w = to_tf32(br1.w);
        *reinterpret_cast<float4*>(&Bs[buf][(brow + 8) * BSTR0 + bcol]) = t;
    };

    auto compute_stage = [&](int buf) {
        const unsigned* Au = reinterpret_cast<const unsigned*>(As[buf]);
        const unsigned* Bu = reinterpret_cast<const unsigned*>(Bs[buf]);
        #pragma unroll
        for (int kk = 0; kk < 2; ++kk) {
            unsigned af[4][4], bf[4][2];
            #pragma unroll
            for (int mt = 0; mt < 4; ++mt) {
                const int r0 = (warpM * 64 + mt * 16 + g) * ASTR + kk * 8 + c;
                af[mt][0] = Au[r0];
                af[mt][1] = Au[r0 + 8 * ASTR];
                af[mt][2] = Au[r0 + 4];
                af[mt][3] = Au[r0 + 8 * ASTR + 4];
            }
            #pragma unroll
            for (int nt = 0; nt < 4; ++nt) {
                const int n0 = warpN * 32 + nt * 8 + g;
                bf[nt][0] = Bu[(kk * 8 + c)     * BSTR0 + n0];
                bf[nt][1] = Bu[(kk * 8 + c + 4) * BSTR0 + n0];
            }
            #pragma unroll
            for (int mt = 0; mt < 4; ++mt)
                #pragma unroll
                for (int nt = 0; nt < 4; ++nt) {
                    asm volatile(
                        "mma.sync.aligned.m16n8k8.row.col.f32.tf32.tf32.f32 "
                        "{%0,%1,%2,%3}, {%4,%5,%6,%7}, {%8,%9}, {%0,%1,%2,%3};"
                        : "+f"(cfr[mt][nt][0]), "+f"(cfr[mt][nt][1]),
                          "+f"(cfr[mt][nt][2]), "+f"(cfr[mt][nt][3])
                        : "r"(af[mt][0]), "r"(af[mt][1]), "r"(af[mt][2]), "r"(af[mt][3]),
                          "r"(bf[nt][0]), "r"(bf[nt][1]));
                }
        }
    };

    int buf = 0;
    ldg_stage(0);
    sts_stage(0);
    __syncthreads();
    for (int k0 = BKT; k0 < K; k0 += BKT) {
        ldg_stage(k0);
        compute_stage(buf);
        sts_stage(buf ^ 1);
        __syncthreads();
        buf ^= 1;
    }
    compute_stage(buf);

    #pragma unroll
    for (int mt = 0; mt < 4; ++mt) {
        const int row = bm + warpM * 64 + mt * 16 + g;
        #pragma unroll
        for (int nt = 0; nt < 4; ++nt) {
            const int col = bn + warpN * 32 + nt * 8 + c * 2;
            #pragma unroll
            for (int half = 0; half < 2; ++half) {
                float* p = Cb + (long long)(row + half * 8) * ldc + col;
                p[0] = cfr[mt][nt][half * 2 + 0];
                p[1] = cfr[mt][nt][half * 2 + 1];
            }
        }
    }
}

// ---------------- batched rowdot ----------------
__global__ void rowdot_kernel(const float* __restrict__ X, ZOffs offs, int nz0, long long s0,
                              int ld, const float* __restrict__ w, float* __restrict__ out,
                              int rows, int Kd)
{
    __shared__ float sm[32];
    const int r = blockIdx.x, z = blockIdx.y;
    const int z1 = z / nz0, z0 = z - z1 * nz0;
    const float* x = X + offs.o[z1] + (long long)z0 * s0 + (long long)r * ld;
    float s = 0.0f;
    for (int k = threadIdx.x; k < Kd; k += 256) s += x[k] * w[k];
    s = blockReduceSum(s, sm);
    if (threadIdx.x == 0) out[(long long)z * rows + r] = s;
}

// ---------------- row softmax in-place ----------------
__global__ void softmax_row_kernel(float* __restrict__ S, int ldS, long long strideS,
                                   const float* __restrict__ kl, int Lk)
{
    __shared__ float sm[32];
    const int q = blockIdx.x, z = blockIdx.y;
    float* row = S + (long long)z * strideS + (long long)q * ldS;
    const float* klb = kl + (long long)z * Lk;

    float v[3];
    int n = 0;
    float m = -3.4e38f;
    for (int k = threadIdx.x; k < Lk; k += 256) {
        float x = row[k] + klb[k];
        v[n++] = x;
        m = fmaxf(m, x);
    }
    m = blockReduceMax(m, sm);
    float s = 0.0f;
    for (int t = 0; t < n; ++t) { v[t] = expf(v[t] - m); s += v[t]; }
    s = blockReduceSum(s, sm);
    const float inv = 1.0f / s;
    n = 0;
    for (int k = threadIdx.x; k < Lk; k += 256) row[k] = v[n++] * inv;
}

// ---------------- column softmax ----------------
__global__ void softmax_col_kernel(const float* __restrict__ S, float* __restrict__ kq,
                                   const float* __restrict__ ql)
{
    const int x = threadIdx.x & 31;
    const int y = threadIdx.x >> 5;
    const int col = blockIdx.x * 32 + x;
    const int z = blockIdx.y;
    const float* Sb = S + (long long)z * (LO * LDOC);
    const float* qlb = ql + (long long)z * LO;

    float vals[LO / 8];
    float m = -3.4e38f;
    #pragma unroll 4
    for (int it = 0; it < LO / 8; ++it) {
        const int r = it * 8 + y;
        float v = qlb[r] + Sb[(long long)r * LDOC + col];
        vals[it] = v;
        m = fmaxf(m, v);
    }
    __shared__ float red[8][32];
    red[y][x] = m;
    __syncthreads();
    if (y == 0) {
        float mm = red[0][x];
        #pragma unroll
        for (int t = 1; t < 8; ++t) mm = fmaxf(mm, red[t][x]);
        red[0][x] = mm;
    }
    __syncthreads();
    m = red[0][x];
    __syncthreads();

    float s = 0.0f;
    #pragma unroll 4
    for (int it = 0; it < LO / 8; ++it) { vals[it] = expf(vals[it] - m); s += vals[it]; }
    red[y][x] = s;
    __syncthreads();
    if (y == 0) {
        float ss = 0.0f;
        #pragma unroll
        for (int t = 0; t < 8; ++t) ss += red[t][x];
        red[0][x] = ss;
    }
    __syncthreads();
    const float inv = 1.0f / red[0][x];

    float* kqb = kq + (long long)z * (LO * LDOC);
    #pragma unroll 4
    for (int it = 0; it < LO / 8; ++it)
        kqb[(long long)(it * 8 + y) * LDOC + col] = vals[it] * inv;
}

// ---------------- final max over positions ----------------
__global__ void maxreduce_kernel(const float* __restrict__ f, float* __restrict__ out)
{
    const int h = blockIdx.x * 256 + threadIdx.x;
    const int b = blockIdx.y;
    float m = -3.4e38f;
    const float* base = f + (long long)b * LO * HD + h;
    #pragma unroll 8
    for (int r = 0; r < LO; ++r) m = fmaxf(m, base[(long long)r * HD]);
    out[(long long)b * HD + h] = m;
}

// ---------------- host ----------------
static ZOffs zzero() { ZOffs z; for (int i = 0; i < 12; ++i) z.o[i] = 0; return z; }

extern "C" void kernel_launch(void* const* d_in, const int* in_sizes, int n_in,
                              void* d_out, int out_size)
{
    const float* last   = (const float*)d_in[4];
    const float* ow2    = (const float*)d_in[6];
    const float* ow3    = (const float*)d_in[7];
    const float* dw1    = (const float*)d_in[8];
    const float* dw2    = (const float*)d_in[9];
    const float* dw3    = (const float*)d_in[10];
    const float* sw2    = (const float*)d_in[12];
    const float* sw3    = (const float*)d_in[13];
    const float* comp_w = (const float*)d_in[14];
    const float* comp_b = (const float*)d_in[15];
    const float* gate_w = (const float*)d_in[16];
    const float* gate_b = (const float*)d_in[17];
    const float* attn_w = (const float*)d_in[18];
    const float* attn_b = (const float*)d_in[19];
    const float* self_w = (const float*)d_in[20];
    const float* self_b = (const float*)d_in[21];

    float *S_, *kq_, *att_, *corr_, *opt_, *a_, *co_, *fus_, *sa_, *cow_, *kl_, *ql_;
    cudaGetSymbolAddress((void**)&S_,   g_S);
    cudaGetSymbolAddress((void**)&kq_,  g_kq);
    cudaGetSymbolAddress((void**)&att_, g_att);
    cudaGetSymbolAddress((void**)&corr_,g_corr);
    cudaGetSymbolAddress((void**)&opt_, g_opt);
    cudaGetSymbolAddress((void**)&a_,   g_a);
    cudaGetSymbolAddress((void**)&co_,  g_co);
    cudaGetSymbolAddress((void**)&fus_, g_fus);
    cudaGetSymbolAddress((void**)&sa_,  g_sa);
    cudaGetSymbolAddress((void**)&cow_, g_cow);
    cudaGetSymbolAddress((void**)&kl_,  g_kl);
    cudaGetSymbolAddress((void**)&ql_,  g_ql);

    const long long sSeq = (long long)SEQ * HD;
    const long long sQ   = 4LL * SEQ * HD;
    const long long LoH  = (long long)LO * HD;

    long long curoff[NL], kvoff[12], attoff[12];
    for (int i = 0; i < NL; ++i) curoff[i] = ((long long)i * SEQ + LDOC) * HD;
    for (int i = 0, p = 0; i < NL; ++i)
        for (int j = 0; j < NL; ++j) {
            if (j == i) continue;
            kvoff[p] = ((long long)j * SEQ + LDOC) * HD;
            attoff[p] = (long long)p * NBZ * LoH;
            ++p;
        }

    // ===== Stage A: 12 pair attentions =====
    {
        ZOffs kvo = zzero();
        for (int p = 0; p < 12; ++p) kvo.o[p] = kvoff[p];
        rowdot_kernel<<<dim3(LO, 96), 256>>>(last, kvo, NBZ, sQ, HD, ow2, kl_, LO, HD);

        ZOffs ao = zzero(), co = zzero();
        for (int p = 0; p < 12; ++p) {
            ao.o[p] = curoff[p / 3];
            co.o[p] = (long long)p * NBZ * LO * LO;
        }
        tgemm_kernel<<<dim3(LO / BN, LO / BM, 96), 256>>>(
            HD, last, HD, sQ, ao, last, HD, sQ, kvo,
            S_, LO, (long long)LO * LO, co, NBZ, ow3);

        softmax_row_kernel<<<dim3(LO, 96), 256>>>(S_, LO, (long long)LO * LO, kl_, LO);

        ZOffs so = co, ato = zzero();
        for (int p = 0; p < 12; ++p) ato.o[p] = attoff[p];
        nngemm_kernel<<<dim3(HD / BN, LO / BM, 96), 256>>>(
            LO, S_, LO, (long long)LO * LO, so, last, HD, sQ, kvo,
            att_, HD, LoH, ato, NBZ);
    }

    // ===== comp: single segmented GEMM, K = 7*1024 =====
    {
        SegArgs sga = {};
        sga.segs[0] = {last, nullptr, (long long)LDOC * HD, (long long)SEQ * HD, sQ, 0, 0, 0, 0, 0};
        for (int m = 0; m < 3; ++m) {
            Seg mulseg = {last, att_, (long long)LDOC * HD, (long long)SEQ * HD, sQ,
                          (long long)m * NBZ * LoH, 3LL * NBZ * LoH, LoH, 1, 0};
            Seg subseg = mulseg; subseg.amode = 2;
            sga.segs[1 + 2 * m] = mulseg;
            sga.segs[2 + 2 * m] = subseg;
        }
        sga.nseg = 7;
        ZOffs co = zzero();
        for (int i = 0; i < NL; ++i) co.o[i] = (long long)i * LoH;
        segk_kernel<<<dim3(HD / BN, LO / BM, 32), 256>>>(
            7 * HD, sga, comp_w, 7 * HD,
            corr_, HD, 4 * LoH, co, NBZ,
            comp_b, 2, nullptr, 0, nullptr, 0);
    }

    // ===== Stage B: gate GEMM with fused blend -> opt =====
    {
        SegArgs sga = {};
        sga.segs[0] = {last, nullptr, (long long)LDOC * HD, 0, sSeq, 0, 0, 0, 0, 0};
        sga.segs[1] = {corr_, nullptr, 0, 0, LoH, 0, 0, 0, 0, 0};
        sga.nseg = 2;
        segk_kernel<<<dim3(HD / BN, LO / BM, 32), 256>>>(
            2 * HD, sga, gate_w, 2 * HD,
            opt_, HD, LoH, zzero(), NBAT,
            gate_b, 4, last + (long long)LDOC * HD, sSeq, corr_, LoH);
    }

    // ===== Stage C: doc attention =====
    {
        ZOffs z0o = zzero();
        rowdot_kernel<<<dim3(LO, NBAT), 256>>>(opt_, z0o, NBAT, LoH, HD, dw1, ql_, LO, HD);
        rowdot_kernel<<<dim3(LDOC, NBAT), 256>>>(last, z0o, NBAT, sSeq, HD, dw2, kl_, LDOC, HD);

        tgemm_kernel<<<dim3(LDOC / BN, LO / BM, 32), 256>>>(
            HD, opt_, HD, LoH, zzero(), last, HD, sSeq, zzero(),
            S_, LDOC, (long long)LO * LDOC, zzero(), NBAT, dw3);

        softmax_col_kernel<<<dim3(LDOC / 32, NBAT), 256>>>(S_, kq_, ql_);
        softmax_row_kernel<<<dim3(LO, NBAT), 256>>>(S_, LDOC, (long long)LO * LDOC, kl_, LDOC);

        nngemm_kernel<<<dim3(HD / BN, LO / BM, 32), 256>>>(
            LDOC, S_, LDOC, (long long)LO * LDOC, zzero(), last, HD, sSeq, zzero(),
            a_, HD, LoH, zzero(), NBAT);

        tgemm_kernel<<<dim3(LO / BN, LO / BM, 32), 256>>>(
            LDOC, S_, LDOC, (long long)LO * LDOC, zzero(), kq_, LDOC, (long long)LO * LDOC, zzero(),
            cow_, LO, (long long)LO * LO, zzero(), NBAT, nullptr);

        nngemm_kernel<<<dim3(HD / BN, LO / BM, 32), 256>>>(
            LO, cow_, LO, (long long)LO * LO, zzero(), opt_, HD, LoH, zzero(),
            co_, HD, LoH, zzero(), NBAT);
    }

    // ===== Stage D: fusion = relu([opt|a|co] @ attn_w^T + b) =====
    {
        SegArgs sga = {};
        sga.segs[0] = {opt_, nullptr, 0, 0, LoH, 0, 0, 0, 0, 0};
        sga.segs[1] = {a_,   nullptr, 0, 0, LoH, 0, 0, 0, 0, 0};
        sga.segs[2] = {co_,  nullptr, 0, 0, LoH, 0, 0, 0, 0, 0};
        sga.nseg = 3;
        segk_kernel<<<dim3(HD / BN, LO / BM, 32), 256>>>(
            3 * HD, sga, attn_w, 3 * HD,
            fus_, HD, LoH, zzero(), NBAT,
            attn_b, 1, nullptr, 0, nullptr, 0);
    }

    // ===== Stage E: self attention =====
    {
        ZOffs z0o = zzero();
        rowdot_kernel<<<dim3(LO, NBAT), 256>>>(fus_, z0o, NBAT, LoH, HD, sw2, kl_, LO, HD);

        tgemm_kernel<<<dim3(LO / BN, LO / BM, 32), 256>>>(
            HD, fus_, HD, LoH, zzero(), fus_, HD, LoH, zzero(),
            S_, LO, (long long)LO * LO, zzero(), NBAT, sw3);

        softmax_row_kernel<<<dim3(LO, NBAT), 256>>>(S_, LO, (long long)LO * LO, kl_, LO);

        nngemm_kernel<<<dim3(HD / BN, LO / BM, 32), 256>>>(
            LO, S_, LO, (long long)LO * LO, zzero(), fus_, HD, LoH, zzero(),
            sa_, HD, LoH, zzero(), NBAT);
    }

    // ===== Stage F: fusion2 = relu([f|sa|f*sa|f-sa] @ self_w^T + b) =====
    {
        SegArgs sga = {};
        sga.segs[0] = {fus_, nullptr, 0, 0, LoH, 0, 0, 0, 0, 0};
        sga.segs[1] = {sa_,  nullptr, 0, 0, LoH, 0, 0, 0, 0, 0};
        sga.segs[2] = {fus_, sa_, 0, 0, LoH, 0, 0, LoH, 1, 0};
        sga.segs[3] = {fus_, sa_, 0, 0, LoH, 0, 0, LoH, 2, 0};
        sga.nseg = 4;
        segk_kernel<<<dim3(HD / BN, LO / BM, 32), 256>>>(
            4 * HD, sga, self_w, 4 * HD,
            corr_, HD, LoH, zzero(), NBAT,
            self_b, 1, nullptr, 0, nullptr, 0);
    }

    // ===== Stage G =====
    maxreduce_kernel<<<dim3(HD / 256, NBAT), 256>>>(corr_, (float*)d_out);
}

// round 7
// speedup vs baseline: 2.4092x; 1.4532x over previous
#include <cuda_runtime.h>
#include <cuda_fp16.h>
#include <math.h>
#include <stdint.h>

#define HD   1024
#define SEQ  1024
#define LO   256
#define LDOC 768
#define NBAT 32
#define NBZ  8
#define NL   4

// ---------------- device scratch ----------------
__device__ float g_S   [96 * LO * LO];
__device__ float g_kq  [NBAT * LO * LDOC];
__device__ float g_att [96 * LO * HD];
__device__ float g_corr[NBAT * LO * HD];
__device__ float g_opt [NBAT * LO * HD];
__device__ float g_a   [NBAT * LO * HD];
__device__ float g_co  [NBAT * LO * HD];
__device__ float g_fus [NBAT * LO * HD];
__device__ float g_sa  [NBAT * LO * HD];
__device__ float g_cow [NBAT * LO * LO];
__device__ float g_kl  [96 * LO];
__device__ float g_ql  [NBAT * LO];

struct ZOffs { long long o[12]; };

struct Seg {
    const float* A;
    const float* A2;
    long long c0, c1, s0;
    long long ac0, ac1, as0;
    int amode;                // 0 none, 1 mul, 2 sub
    int pad;
};
struct SegArgs { Seg segs[8]; int nseg; };

// ---------------- helpers ----------------
__device__ __forceinline__ float to_tf32(float x) {
    unsigned u;
    asm("cvt.rna.tf32.f32 %0, %1;" : "=r"(u) : "f"(x));
    return __uint_as_float(u);
}

__device__ __forceinline__ unsigned ph2(float lo, float hi) {
    __half2 h = __floats2half2_rn(lo, hi);
    return *reinterpret_cast<unsigned*>(&h);
}

__device__ __forceinline__ float blockReduceMax(float v, float* sm) {
    #pragma unroll
    for (int o = 16; o; o >>= 1) v = fmaxf(v, __shfl_xor_sync(0xffffffffu, v, o));
    int w = threadIdx.x >> 5;
    if ((threadIdx.x & 31) == 0) sm[w] = v;
    __syncthreads();
    if (threadIdx.x < 32) {
        v = (threadIdx.x < (blockDim.x >> 5)) ? sm[threadIdx.x] : -3.4e38f;
        #pragma unroll
        for (int o = 4; o; o >>= 1) v = fmaxf(v, __shfl_xor_sync(0xffffffffu, v, o));
        if (threadIdx.x == 0) sm[0] = v;
    }
    __syncthreads();
    v = sm[0];
    __syncthreads();
    return v;
}

__device__ __forceinline__ float blockReduceSum(float v, float* sm) {
    #pragma unroll
    for (int o = 16; o; o >>= 1) v += __shfl_xor_sync(0xffffffffu, v, o);
    int w = threadIdx.x >> 5;
    if ((threadIdx.x & 31) == 0) sm[w] = v;
    __syncthreads();
    if (threadIdx.x < 32) {
        v = (threadIdx.x < (blockDim.x >> 5)) ? sm[threadIdx.x] : 0.0f;
        #pragma unroll
        for (int o = 4; o; o >>= 1) v += __shfl_xor_sync(0xffffffffu, v, o);
        if (threadIdx.x == 0) sm[0] = v;
    }
    __syncthreads();
    v = sm[0];
    __syncthreads();
    return v;
}

#define BM 128
#define BN 128
#define BKT 16
#define ASTR (BKT + 4)     // 20 u32 per tile row (NT fp16: 32 halves in 16 u32; tf32: 16 floats)
#define BSTR0 (BN + 8)

// ======== fp16 NT fragment compute: 8 warps 2x4, 64x32 warp tile, k16 per mma ======
#define NT16_COMPUTE_STAGE(Au, Bu)                                                   \
    _Pragma("unroll")                                                                \
    for (int kk = 0; kk < 2; ++kk) {                                                 \
        unsigned af[4][4], bf[4][2];                                                 \
        _Pragma("unroll")                                                            \
        for (int mt = 0; mt < 4; ++mt) {                                             \
            const int r0 = (warpM * 64 + mt * 16 + g) * ASTR + kk * 8 + c;           \
            af[mt][0] = Au[r0];                                                      \
            af[mt][1] = Au[r0 + 8 * ASTR];                                           \
            af[mt][2] = Au[r0 + 4];                                                  \
            af[mt][3] = Au[r0 + 8 * ASTR + 4];                                       \
        }                                                                            \
        _Pragma("unroll")                                                            \
        for (int nt = 0; nt < 4; ++nt) {                                             \
            const int n0 = warpN * 32 + nt * 8 + g;                                  \
            bf[nt][0] = Bu[n0 * ASTR + kk * 8 + c];                                  \
            bf[nt][1] = Bu[n0 * ASTR + kk * 8 + c + 4];                              \
        }                                                                            \
        _Pragma("unroll")                                                            \
        for (int mt = 0; mt < 4; ++mt)                                               \
            _Pragma("unroll")                                                        \
            for (int nt = 0; nt < 4; ++nt) {                                         \
                asm volatile(                                                        \
                    "mma.sync.aligned.m16n8k16.row.col.f32.f16.f16.f32 "             \
                    "{%0,%1,%2,%3}, {%4,%5,%6,%7}, {%8,%9}, {%0,%1,%2,%3};"          \
                    : "+f"(cfr[mt][nt][0]), "+f"(cfr[mt][nt][1]),                    \
                      "+f"(cfr[mt][nt][2]), "+f"(cfr[mt][nt][3])                     \
                    : "r"(af[mt][0]), "r"(af[mt][1]), "r"(af[mt][2]), "r"(af[mt][3]),\
                      "r"(bf[nt][0]), "r"(bf[nt][1]));                               \
            }                                                                        \
    }

// ================= fp16 NT GEMM: C = A @ B^T (S-matrices, cow) ======================
__global__ __launch_bounds__(256, 2)
void tgemm_kernel(int K,
                  const float* __restrict__ A, int lda, long long sA0, ZOffs aoffs,
                  const float* __restrict__ B, int ldb, long long sB0, ZOffs boffs,
                  float* __restrict__ C, int ldc, long long sC0, ZOffs coffs,
                  int nz0, const float* __restrict__ ascale)
{
    __shared__ unsigned As[2][BM * ASTR];
    __shared__ unsigned Bs[2][BN * ASTR];

    const int z  = blockIdx.z;
    const int z1 = z / nz0;
    const int z0 = z - z1 * nz0;
    const float* Ab = A + aoffs.o[z1] + (long long)z0 * sA0;
    const float* Bb = B + boffs.o[z1] + (long long)z0 * sB0;
    float*       Cb = C + coffs.o[z1] + (long long)z0 * sC0;

    const int bm = blockIdx.y * BM;
    const int bn = blockIdx.x * BN;
    const int tid  = threadIdx.x;
    const int lane = tid & 31;
    const int warp = tid >> 5;
    const int warpM = warp >> 2;
    const int warpN = warp & 3;
    const int g = lane >> 2;
    const int c = lane & 3;

    const int arow = tid >> 2;      // 0..63
    const int ac4  = tid & 3;       // k-elem base = ac4*8

    uint4 au0, au1, bu0, bu1;       // packed half2 staging

    float cfr[4][4][4];
    #pragma unroll
    for (int mt = 0; mt < 4; ++mt)
        #pragma unroll
        for (int nt = 0; nt < 4; ++nt)
            #pragma unroll
            for (int r = 0; r < 4; ++r) cfr[mt][nt][r] = 0.0f;

    auto ldg_stage = [&](int k0) {
        const int ke = k0 + ac4 * 8;
        float4 x0 = *reinterpret_cast<const float4*>(Ab + (long long)(bm + arow) * lda + ke);
        float4 x1 = *reinterpret_cast<const float4*>(Ab + (long long)(bm + arow) * lda + ke + 4);
        float4 y0 = *reinterpret_cast<const float4*>(Ab + (long long)(bm + arow + 64) * lda + ke);
        float4 y1 = *reinterpret_cast<const float4*>(Ab + (long long)(bm + arow + 64) * lda + ke + 4);
        if (ascale) {
            float s0 = ascale[ke + 0], s1 = ascale[ke + 1], s2 = ascale[ke + 2], s3 = ascale[ke + 3];
            float s4 = ascale[ke + 4], s5 = ascale[ke + 5], s6 = ascale[ke + 6], s7 = ascale[ke + 7];
            x0.x *= s0; x0.y *= s1; x0.z *= s2; x0.w *= s3;
            x1.x *= s4; x1.y *= s5; x1.z *= s6; x1.w *= s7;
            y0.x *= s0; y0.y *= s1; y0.z *= s2; y0.w *= s3;
            y1.x *= s4; y1.y *= s5; y1.z *= s6; y1.w *= s7;
        }
        au0 = make_uint4(ph2(x0.x, x0.y), ph2(x0.z, x0.w), ph2(x1.x, x1.y), ph2(x1.z, x1.w));
        au1 = make_uint4(ph2(y0.x, y0.y), ph2(y0.z, y0.w), ph2(y1.x, y1.y), ph2(y1.z, y1.w));
        float4 p0 = *reinterpret_cast<const float4*>(Bb + (long long)(bn + arow) * ldb + ke);
        float4 p1 = *reinterpret_cast<const float4*>(Bb + (long long)(bn + arow) * ldb + ke + 4);
        float4 q0 = *reinterpret_cast<const float4*>(Bb + (long long)(bn + arow + 64) * ldb + ke);
        float4 q1 = *reinterpret_cast<const float4*>(Bb + (long long)(bn + arow + 64) * ldb + ke + 4);
        bu0 = make_uint4(ph2(p0.x, p0.y), ph2(p0.z, p0.w), ph2(p1.x, p1.y), ph2(p1.z, p1.w));
        bu1 = make_uint4(ph2(q0.x, q0.y), ph2(q0.z, q0.w), ph2(q1.x, q1.y), ph2(q1.z, q1.w));
    };

    auto sts_stage = [&](int buf) {
        *reinterpret_cast<uint4*>(&As[buf][arow * ASTR + ac4 * 4]) = au0;
        *reinterpret_cast<uint4*>(&As[buf][(arow + 64) * ASTR + ac4 * 4]) = au1;
        *reinterpret_cast<uint4*>(&Bs[buf][arow * ASTR + ac4 * 4]) = bu0;
        *reinterpret_cast<uint4*>(&Bs[buf][(arow + 64) * ASTR + ac4 * 4]) = bu1;
    };

    int buf = 0;
    ldg_stage(0);
    sts_stage(0);
    __syncthreads();
    for (int k0 = 32; k0 < K; k0 += 32) {
        ldg_stage(k0);
        {
            const unsigned* Au = As[buf];
            const unsigned* Bu = Bs[buf];
            NT16_COMPUTE_STAGE(Au, Bu)
        }
        sts_stage(buf ^ 1);
        __syncthreads();
        buf ^= 1;
    }
    {
        const unsigned* Au = As[buf];
        const unsigned* Bu = Bs[buf];
        NT16_COMPUTE_STAGE(Au, Bu)
    }

    #pragma unroll
    for (int mt = 0; mt < 4; ++mt) {
        const int row = bm + warpM * 64 + mt * 16 + g;
        #pragma unroll
        for (int nt = 0; nt < 4; ++nt) {
            const int col = bn + warpN * 32 + nt * 8 + c * 2;
            #pragma unroll
            for (int half = 0; half < 2; ++half) {
                float* p = Cb + (long long)(row + half * 8) * ldc + col;
                p[0] = cfr[mt][nt][half * 2 + 0];
                p[1] = cfr[mt][nt][half * 2 + 1];
            }
        }
    }
}

// ================= fp16 segmented-K NT GEMM (concat in K, fused epilogue) ===========
// act: 0 none, 1 relu, 2 tanh, 4 gate: out = e1*sig(v) + e2*(1-sig(v))
__global__ __launch_bounds__(256, 2)
void segk_kernel(int Ktot, SegArgs sga,
                 const float* __restrict__ B, int ldb,
                 float* __restrict__ C, int ldc, long long sC0, ZOffs coffs, int nz0,
                 const float* __restrict__ bias, int act,
                 const float* __restrict__ e1, long long e1s,
                 const float* __restrict__ e2, long long e2s)
{
    __shared__ unsigned As[2][BM * ASTR];
    __shared__ unsigned Bs[2][BN * ASTR];

    const int z  = blockIdx.z;
    const int z1 = z / nz0;
    const int z0 = z - z1 * nz0;
    float* Cb = C + coffs.o[z1] + (long long)z0 * sC0;

    const int bm = blockIdx.y * BM;
    const int bn = blockIdx.x * BN;
    const int tid  = threadIdx.x;
    const int lane = tid & 31;
    const int warp = tid >> 5;
    const int warpM = warp >> 2;
    const int warpN = warp & 3;
    const int g = lane >> 2;
    const int c = lane & 3;

    const int arow = tid >> 2;
    const int ac4  = tid & 3;

    int curseg = -1;
    const float* Ab = nullptr;
    const float* A2b = nullptr;
    int am = 0;

    uint4 au0, au1, bu0, bu1;

    float cfr[4][4][4];
    #pragma unroll
    for (int mt = 0; mt < 4; ++mt)
        #pragma unroll
        for (int nt = 0; nt < 4; ++nt)
            #pragma unroll
            for (int r = 0; r < 4; ++r) cfr[mt][nt][r] = 0.0f;

    auto ldg_stage = [&](int k0) {
        const int s = k0 >> 10;
        if (s != curseg) {
            curseg = s;
            const Seg& sg = sga.segs[s];
            Ab = sg.A + sg.c0 + sg.c1 * z1 + sg.s0 * z0;
            am = sg.amode;
            A2b = am ? (sg.A2 + sg.ac0 + sg.ac1 * z1 + sg.as0 * z0) : nullptr;
        }
        const int kl = (k0 & 1023) + ac4 * 8;
        float4 x0 = *reinterpret_cast<const float4*>(Ab + (long long)(bm + arow) * 1024 + kl);
        float4 x1 = *reinterpret_cast<const float4*>(Ab + (long long)(bm + arow) * 1024 + kl + 4);
        float4 y0 = *reinterpret_cast<const float4*>(Ab + (long long)(bm + arow + 64) * 1024 + kl);
        float4 y1 = *reinterpret_cast<const float4*>(Ab + (long long)(bm + arow + 64) * 1024 + kl + 4);
        if (am) {
            float4 u0 = *reinterpret_cast<const float4*>(A2b + (long long)(bm + arow) * 1024 + kl);
            float4 u1 = *reinterpret_cast<const float4*>(A2b + (long long)(bm + arow) * 1024 + kl + 4);
            float4 v0 = *reinterpret_cast<const float4*>(A2b + (long long)(bm + arow + 64) * 1024 + kl);
            float4 v1 = *reinterpret_cast<const float4*>(A2b + (long long)(bm + arow + 64) * 1024 + kl + 4);
            if (am == 1) {
                x0.x *= u0.x; x0.y *= u0.y; x0.z *= u0.z; x0.w *= u0.w;
                x1.x *= u1.x; x1.y *= u1.y; x1.z *= u1.z; x1.w *= u1.w;
                y0.x *= v0.x; y0.y *= v0.y; y0.z *= v0.z; y0.w *= v0.w;
                y1.x *= v1.x; y1.y *= v1.y; y1.z *= v1.z; y1.w *= v1.w;
            } else {
                x0.x -= u0.x; x0.y -= u0.y; x0.z -= u0.z; x0.w -= u0.w;
                x1.x -= u1.x; x1.y -= u1.y; x1.z -= u1.z; x1.w -= u1.w;
                y0.x -= v0.x; y0.y -= v0.y; y0.z -= v0.z; y0.w -= v0.w;
                y1.x -= v1.x; y1.y -= v1.y; y1.z -= v1.z; y1.w -= v1.w;
            }
        }
        au0 = make_uint4(ph2(x0.x, x0.y), ph2(x0.z, x0.w), ph2(x1.x, x1.y), ph2(x1.z, x1.w));
        au1 = make_uint4(ph2(y0.x, y0.y), ph2(y0.z, y0.w), ph2(y1.x, y1.y), ph2(y1.z, y1.w));
        const int ke = k0 + ac4 * 8;
        float4 p0 = *reinterpret_cast<const float4*>(B + (long long)(bn + arow) * ldb + ke);
        float4 p1 = *reinterpret_cast<const float4*>(B + (long long)(bn + arow) * ldb + ke + 4);
        float4 q0 = *reinterpret_cast<const float4*>(B + (long long)(bn + arow + 64) * ldb + ke);
        float4 q1 = *reinterpret_cast<const float4*>(B + (long long)(bn + arow + 64) * ldb + ke + 4);
        bu0 = make_uint4(ph2(p0.x, p0.y), ph2(p0.z, p0.w), ph2(p1.x, p1.y), ph2(p1.z, p1.w));
        bu1 = make_uint4(ph2(q0.x, q0.y), ph2(q0.z, q0.w), ph2(q1.x, q1.y), ph2(q1.z, q1.w));
    };

    auto sts_stage = [&](int buf) {
        *reinterpret_cast<uint4*>(&As[buf][arow * ASTR + ac4 * 4]) = au0;
        *reinterpret_cast<uint4*>(&As[buf][(arow + 64) * ASTR + ac4 * 4]) = au1;
        *reinterpret_cast<uint4*>(&Bs[buf][arow * ASTR + ac4 * 4]) = bu0;
        *reinterpret_cast<uint4*>(&Bs[buf][(arow + 64) * ASTR + ac4 * 4]) = bu1;
    };

    int buf = 0;
    ldg_stage(0);
    sts_stage(0);
    __syncthreads();
    for (int k0 = 32; k0 < Ktot; k0 += 32) {
        ldg_stage(k0);
        {
            const unsigned* Au = As[buf];
            const unsigned* Bu = Bs[buf];
            NT16_COMPUTE_STAGE(Au, Bu)
        }
        sts_stage(buf ^ 1);
        __syncthreads();
        buf ^= 1;
    }
    {
        const unsigned* Au = As[buf];
        const unsigned* Bu = Bs[buf];
        NT16_COMPUTE_STAGE(Au, Bu)
    }

    #pragma unroll
    for (int mt = 0; mt < 4; ++mt) {
        const int row = bm + warpM * 64 + mt * 16 + g;
        #pragma unroll
        for (int nt = 0; nt < 4; ++nt) {
            const int col = bn + warpN * 32 + nt * 8 + c * 2;
            #pragma unroll
            for (int half = 0; half < 2; ++half) {
                const int r2 = row + half * 8;
                float* p = Cb + (long long)r2 * ldc + col;
                float v0 = cfr[mt][nt][half * 2 + 0];
                float v1 = cfr[mt][nt][half * 2 + 1];
                if (bias) { v0 += bias[col]; v1 += bias[col + 1]; }
                if (act == 1)      { v0 = fmaxf(v0, 0.0f); v1 = fmaxf(v1, 0.0f); }
                else if (act == 2) { v0 = tanhf(v0); v1 = tanhf(v1); }
                else if (act == 4) {
                    const float g0 = 1.0f / (1.0f + expf(-v0));
                    const float g1 = 1.0f / (1.0f + expf(-v1));
                    const float* pe = e1 + (long long)z0 * e1s + (long long)r2 * ldc + col;
                    const float* pc = e2 + (long long)z0 * e2s + (long long)r2 * ldc + col;
                    v0 = pe[0] * g0 + pc[0] * (1.0f - g0);
                    v1 = pe[1] * g1 + pc[1] * (1.0f - g1);
                }
                p[0] = v0; p[1] = v1;
            }
        }
    }
}

// ================= tf32 NN GEMM (P@V etc., unchanged proven path) =================
__global__ __launch_bounds__(256, 2)
void nngemm_kernel(int K,
                   const float* __restrict__ A, int lda, long long sA0, ZOffs aoffs,
                   const float* __restrict__ B, int ldb, long long sB0, ZOffs boffs,
                   float* __restrict__ C, int ldc, long long sC0, ZOffs coffs,
                   int nz0)
{
    __shared__ float As[2][BM * ASTR];
    __shared__ float Bs[2][BKT * BSTR0];

    const int z  = blockIdx.z;
    const int z1 = z / nz0;
    const int z0 = z - z1 * nz0;
    const float* Ab = A + aoffs.o[z1] + (long long)z0 * sA0;
    const float* Bb = B + boffs.o[z1] + (long long)z0 * sB0;
    float*       Cb = C + coffs.o[z1] + (long long)z0 * sC0;

    const int bm = blockIdx.y * BM;
    const int bn = blockIdx.x * BN;
    const int tid  = threadIdx.x;
    const int lane = tid & 31;
    const int warp = tid >> 5;
    const int warpM = warp >> 2;
    const int warpN = warp & 3;
    const int g = lane >> 2;
    const int c = lane & 3;

    const int arow = tid >> 2;
    const int ac4  = tid & 3;
    const int brow = tid >> 5;
    const int bcol = (tid & 31) * 4;

    float4 ar0, ar1, br0, br1;

    float cfr[4][4][4];
    #pragma unroll
    for (int mt = 0; mt < 4; ++mt)
        #pragma unroll
        for (int nt = 0; nt < 4; ++nt)
            #pragma unroll
            for (int r = 0; r < 4; ++r) cfr[mt][nt][r] = 0.0f;

    auto ldg_stage = [&](int k0) {
        ar0 = *reinterpret_cast<const float4*>(Ab + (long long)(bm + arow)      * lda + k0 + ac4 * 4);
        ar1 = *reinterpret_cast<const float4*>(Ab + (long long)(bm + arow + 64) * lda + k0 + ac4 * 4);
        br0 = *reinterpret_cast<const float4*>(Bb + (long long)(k0 + brow)     * ldb + bn + bcol);
        br1 = *reinterpret_cast<const float4*>(Bb + (long long)(k0 + brow + 8) * ldb + bn + bcol);
    };

    auto sts_stage = [&](int buf) {
        float4 t;
        t.x = to_tf32(ar0.x); t.y = to_tf32(ar0.y); t.z = to_tf32(ar0.z); t.w = to_tf32(ar0.w);
        *reinterpret_cast<float4*>(&As[buf][arow * ASTR + ac4 * 4]) = t;
        t.x = to_tf32(ar1.x); t.y = to_tf32(ar1.y); t.z = to_tf32(ar1.z); t.w = to_tf32(ar1.w);
        *reinterpret_cast<float4*>(&As[buf][(arow + 64) * ASTR + ac4 * 4]) = t;
        t.x = to_tf32(br0.x); t.y = to_tf32(br0.y); t.z = to_tf32(br0.z); t.w = to_tf32(br0.w);
        *reinterpret_cast<float4*>(&Bs[buf][brow * BSTR0 + bcol]) = t;
        t.x = to_tf32(br1.x); t.y = to_tf32(br1.y); t.z = to_tf32(br1.z); t.w = to_tf32(br1.w);
        *reinterpret_cast<float4*>(&Bs[buf][(brow + 8) * BSTR0 + bcol]) = t;
    };

    auto compute_stage = [&](int buf) {
        const unsigned* Au = reinterpret_cast<const unsigned*>(As[buf]);
        const unsigned* Bu = reinterpret_cast<const unsigned*>(Bs[buf]);
        #pragma unroll
        for (int kk = 0; kk < 2; ++kk) {
            unsigned af[4][4], bf[4][2];
            #pragma unroll
            for (int mt = 0; mt < 4; ++mt) {
                const int r0 = (warpM * 64 + mt * 16 + g) * ASTR + kk * 8 + c;
                af[mt][0] = Au[r0];
                af[mt][1] = Au[r0 + 8 * ASTR];
                af[mt][2] = Au[r0 + 4];
                af[mt][3] = Au[r0 + 8 * ASTR + 4];
            }
            #pragma unroll
            for (int nt = 0; nt < 4; ++nt) {
                const int n0 = warpN * 32 + nt * 8 + g;
                bf[nt][0] = Bu[(kk * 8 + c)     * BSTR0 + n0];
                bf[nt][1] = Bu[(kk * 8 + c + 4) * BSTR0 + n0];
            }
            #pragma unroll
            for (int mt = 0; mt < 4; ++mt)
                #pragma unroll
                for (int nt = 0; nt < 4; ++nt) {
                    asm volatile(
                        "mma.sync.aligned.m16n8k8.row.col.f32.tf32.tf32.f32 "
                        "{%0,%1,%2,%3}, {%4,%5,%6,%7}, {%8,%9}, {%0,%1,%2,%3};"
                        : "+f"(cfr[mt][nt][0]), "+f"(cfr[mt][nt][1]),
                          "+f"(cfr[mt][nt][2]), "+f"(cfr[mt][nt][3])
                        : "r"(af[mt][0]), "r"(af[mt][1]), "r"(af[mt][2]), "r"(af[mt][3]),
                          "r"(bf[nt][0]), "r"(bf[nt][1]));
                }
        }
    };

    int buf = 0;
    ldg_stage(0);
    sts_stage(0);
    __syncthreads();
    for (int k0 = BKT; k0 < K; k0 += BKT) {
        ldg_stage(k0);
        compute_stage(buf);
        sts_stage(buf ^ 1);
        __syncthreads();
        buf ^= 1;
    }
    compute_stage(buf);

    #pragma unroll
    for (int mt = 0; mt < 4; ++mt) {
        const int row = bm + warpM * 64 + mt * 16 + g;
        #pragma unroll
        for (int nt = 0; nt < 4; ++nt) {
            const int col = bn + warpN * 32 + nt * 8 + c * 2;
            #pragma unroll
            for (int half = 0; half < 2; ++half) {
                float* p = Cb + (long long)(row + half * 8) * ldc + col;
                p[0] = cfr[mt][nt][half * 2 + 0];
                p[1] = cfr[mt][nt][half * 2 + 1];
            }
        }
    }
}

// ---------------- batched rowdot ----------------
__global__ void rowdot_kernel(const float* __restrict__ X, ZOffs offs, int nz0, long long s0,
                              int ld, const float* __restrict__ w, float* __restrict__ out,
                              int rows, int Kd)
{
    __shared__ float sm[32];
    const int r = blockIdx.x, z = blockIdx.y;
    const int z1 = z / nz0, z0 = z - z1 * nz0;
    const float* x = X + offs.o[z1] + (long long)z0 * s0 + (long long)r * ld;
    float s = 0.0f;
    for (int k = threadIdx.x; k < Kd; k += 256) s += x[k] * w[k];
    s = blockReduceSum(s, sm);
    if (threadIdx.x == 0) out[(long long)z * rows + r] = s;
}

// ---------------- row softmax in-place ----------------
__global__ void softmax_row_kernel(float* __restrict__ S, int ldS, long long strideS,
                                   const float* __restrict__ kl, int Lk)
{
    __shared__ float sm[32];
    const int q = blockIdx.x, z = blockIdx.y;
    float* row = S + (long long)z * strideS + (long long)q * ldS;
    const float* klb = kl + (long long)z * Lk;

    float v[3];
    int n = 0;
    float m = -3.4e38f;
    for (int k = threadIdx.x; k < Lk; k += 256) {
        float x = row[k] + klb[k];
        v[n++] = x;
        m = fmaxf(m, x);
    }
    m = blockReduceMax(m, sm);
    float s = 0.0f;
    for (int t = 0; t < n; ++t) { v[t] = expf(v[t] - m); s += v[t]; }
    s = blockReduceSum(s, sm);
    const float inv = 1.0f / s;
    n = 0;
    for (int k = threadIdx.x; k < Lk; k += 256) row[k] = v[n++] * inv;
}

// ---------------- column softmax ----------------
__global__ void softmax_col_kernel(const float* __restrict__ S, float* __restrict__ kq,
                                   const float* __restrict__ ql)
{
    const int x = threadIdx.x & 31;
    const int y = threadIdx.x >> 5;
    const int col = blockIdx.x * 32 + x;
    const int z = blockIdx.y;
    const float* Sb = S + (long long)z * (LO * LDOC);
    const float* qlb = ql + (long long)z * LO;

    float vals[LO / 8];
    float m = -3.4e38f;
    #pragma unroll 4
    for (int it = 0; it < LO / 8; ++it) {
        const int r = it * 8 + y;
        float v = qlb[r] + Sb[(long long)r * LDOC + col];
        vals[it] = v;
        m = fmaxf(m, v);
    }
    __shared__ float red[8][32];
    red[y][x] = m;
    __syncthreads();
    if (y == 0) {
        float mm = red[0][x];
        #pragma unroll
        for (int t = 1; t < 8; ++t) mm = fmaxf(mm, red[t][x]);
        red[0][x] = mm;
    }
    __syncthreads();
    m = red[0][x];
    __syncthreads();

    float s = 0.0f;
    #pragma unroll 4
    for (int it = 0; it < LO / 8; ++it) { vals[it] = expf(vals[it] - m); s += vals[it]; }
    red[y][x] = s;
    __syncthreads();
    if (y == 0) {
        float ss = 0.0f;
        #pragma unroll
        for (int t = 0; t < 8; ++t) ss += red[t][x];
        red[0][x] = ss;
    }
    __syncthreads();
    const float inv = 1.0f / red[0][x];

    float* kqb = kq + (long long)z * (LO * LDOC);
    #pragma unroll 4
    for (int it = 0; it < LO / 8; ++it)
        kqb[(long long)(it * 8 + y) * LDOC + col] = vals[it] * inv;
}

// ---------------- final max over positions ----------------
__global__ void maxreduce_kernel(const float* __restrict__ f, float* __restrict__ out)
{
    const int h = blockIdx.x * 256 + threadIdx.x;
    const int b = blockIdx.y;
    float m = -3.4e38f;
    const float* base = f + (long long)b * LO * HD + h;
    #pragma unroll 8
    for (int r = 0; r < LO; ++r) m = fmaxf(m, base[(long long)r * HD]);
    out[(long long)b * HD + h] = m;
}

// ---------------- host ----------------
static ZOffs zzero() { ZOffs z; for (int i = 0; i < 12; ++i) z.o[i] = 0; return z; }

extern "C" void kernel_launch(void* const* d_in, const int* in_sizes, int n_in,
                              void* d_out, int out_size)
{
    const float* last   = (const float*)d_in[4];
    const float* ow2    = (const float*)d_in[6];
    const float* ow3    = (const float*)d_in[7];
    const float* dw1    = (const float*)d_in[8];
    const float* dw2    = (const float*)d_in[9];
    const float* dw3    = (const float*)d_in[10];
    const float* sw2    = (const float*)d_in[12];
    const float* sw3    = (const float*)d_in[13];
    const float* comp_w = (const float*)d_in[14];
    const float* comp_b = (const float*)d_in[15];
    const float* gate_w = (const float*)d_in[16];
    const float* gate_b = (const float*)d_in[17];
    const float* attn_w = (const float*)d_in[18];
    const float* attn_b = (const float*)d_in[19];
    const float* self_w = (const float*)d_in[20];
    const float* self_b = (const float*)d_in[21];

    float *S_, *kq_, *att_, *corr_, *opt_, *a_, *co_, *fus_, *sa_, *cow_, *kl_, *ql_;
    cudaGetSymbolAddress((void**)&S_,   g_S);
    cudaGetSymbolAddress((void**)&kq_,  g_kq);
    cudaGetSymbolAddress((void**)&att_, g_att);
    cudaGetSymbolAddress((void**)&corr_,g_corr);
    cudaGetSymbolAddress((void**)&opt_, g_opt);
    cudaGetSymbolAddress((void**)&a_,   g_a);
    cudaGetSymbolAddress((void**)&co_,  g_co);
    cudaGetSymbolAddress((void**)&fus_, g_fus);
    cudaGetSymbolAddress((void**)&sa_,  g_sa);
    cudaGetSymbolAddress((void**)&cow_, g_cow);
    cudaGetSymbolAddress((void**)&kl_,  g_kl);
    cudaGetSymbolAddress((void**)&ql_,  g_ql);

    const long long sSeq = (long long)SEQ * HD;
    const long long sQ   = 4LL * SEQ * HD;
    const long long LoH  = (long long)LO * HD;

    long long curoff[NL], kvoff[12], attoff[12];
    for (int i = 0; i < NL; ++i) curoff[i] = ((long long)i * SEQ + LDOC) * HD;
    for (int i = 0, p = 0; i < NL; ++i)
        for (int j = 0; j < NL; ++j) {
            if (j == i) continue;
            kvoff[p] = ((long long)j * SEQ + LDOC) * HD;
            attoff[p] = (long long)p * NBZ * LoH;
            ++p;
        }

    // ===== Stage A: 12 pair attentions =====
    {
        ZOffs kvo = zzero();
        for (int p = 0; p < 12; ++p) kvo.o[p] = kvoff[p];
        rowdot_kernel<<<dim3(LO, 96), 256>>>(last, kvo, NBZ, sQ, HD, ow2, kl_, LO, HD);

        ZOffs ao = zzero(), co = zzero();
        for (int p = 0; p < 12; ++p) {
            ao.o[p] = curoff[p / 3];
            co.o[p] = (long long)p * NBZ * LO * LO;
        }
        tgemm_kernel<<<dim3(LO / BN, LO / BM, 96), 256>>>(
            HD, last, HD, sQ, ao, last, HD, sQ, kvo,
            S_, LO, (long long)LO * LO, co, NBZ, ow3);

        softmax_row_kernel<<<dim3(LO, 96), 256>>>(S_, LO, (long long)LO * LO, kl_, LO);

        ZOffs so = co, ato = zzero();
        for (int p = 0; p < 12; ++p) ato.o[p] = attoff[p];
        nngemm_kernel<<<dim3(HD / BN, LO / BM, 96), 256>>>(
            LO, S_, LO, (long long)LO * LO, so, last, HD, sQ, kvo,
            att_, HD, LoH, ato, NBZ);
    }

    // ===== comp: single segmented GEMM, K = 7*1024 =====
    {
        SegArgs sga = {};
        sga.segs[0] = {last, nullptr, (long long)LDOC * HD, (long long)SEQ * HD, sQ, 0, 0, 0, 0, 0};
        for (int m = 0; m < 3; ++m) {
            Seg mulseg = {last, att_, (long long)LDOC * HD, (long long)SEQ * HD, sQ,
                          (long long)m * NBZ * LoH, 3LL * NBZ * LoH, LoH, 1, 0};
            Seg subseg = mulseg; subseg.amode = 2;
            sga.segs[1 + 2 * m] = mulseg;
            sga.segs[2 + 2 * m] = subseg;
        }
        sga.nseg = 7;
        ZOffs co = zzero();
        for (int i = 0; i < NL; ++i) co.o[i] = (long long)i * LoH;
        segk_kernel<<<dim3(HD / BN, LO / BM, 32), 256>>>(
            7 * HD, sga, comp_w, 7 * HD,
            corr_, HD, 4 * LoH, co, NBZ,
            comp_b, 2, nullptr, 0, nullptr, 0);
    }

    // ===== Stage B: gate GEMM with fused blend -> opt =====
    {
        SegArgs sga = {};
        sga.segs[0] = {last, nullptr, (long long)LDOC * HD, 0, sSeq, 0, 0, 0, 0, 0};
        sga.segs[1] = {corr_, nullptr, 0, 0, LoH, 0, 0, 0, 0, 0};
        sga.nseg = 2;
        segk_kernel<<<dim3(HD / BN, LO / BM, 32), 256>>>(
            2 * HD, sga, gate_w, 2 * HD,
            opt_, HD, LoH, zzero(), NBAT,
            gate_b, 4, last + (long long)LDOC * HD, sSeq, corr_, LoH);
    }

    // ===== Stage C: doc attention =====
    {
        ZOffs z0o = zzero();
        rowdot_kernel<<<dim3(LO, NBAT), 256>>>(opt_, z0o, NBAT, LoH, HD, dw1, ql_, LO, HD);
        rowdot_kernel<<<dim3(LDOC, NBAT), 256>>>(last, z0o, NBAT, sSeq, HD, dw2, kl_, LDOC, HD);

        tgemm_kernel<<<dim3(LDOC / BN, LO / BM, 32), 256>>>(
            HD, opt_, HD, LoH, zzero(), last, HD, sSeq, zzero(),
            S_, LDOC, (long long)LO * LDOC, zzero(), NBAT, dw3);

        softmax_col_kernel<<<dim3(LDOC / 32, NBAT), 256>>>(S_, kq_, ql_);
        softmax_row_kernel<<<dim3(LO, NBAT), 256>>>(S_, LDOC, (long long)LO * LDOC, kl_, LDOC);

        nngemm_kernel<<<dim3(HD / BN, LO / BM, 32), 256>>>(
            LDOC, S_, LDOC, (long long)LO * LDOC, zzero(), last, HD, sSeq, zzero(),
            a_, HD, LoH, zzero(), NBAT);

        tgemm_kernel<<<dim3(LO / BN, LO / BM, 32), 256>>>(
            LDOC, S_, LDOC, (long long)LO * LDOC, zzero(), kq_, LDOC, (long long)LO * LDOC, zzero(),
            cow_, LO, (long long)LO * LO, zzero(), NBAT, nullptr);

        nngemm_kernel<<<dim3(HD / BN, LO / BM, 32), 256>>>(
            LO, cow_, LO, (long long)LO * LO, zzero(), opt_, HD, LoH, zzero(),
            co_, HD, LoH, zzero(), NBAT);
    }

    // ===== Stage D: fusion = relu([opt|a|co] @ attn_w^T + b) =====
    {
        SegArgs sga = {};
        sga.segs[0] = {opt_, nullptr, 0, 0, LoH, 0, 0, 0, 0, 0};
        sga.segs[1] = {a_,   nullptr, 0, 0, LoH, 0, 0, 0, 0, 0};
        sga.segs[2] = {co_,  nullptr, 0, 0, LoH, 0, 0, 0, 0, 0};
        sga.nseg = 3;
        segk_kernel<<<dim3(HD / BN, LO / BM, 32), 256>>>(
            3 * HD, sga, attn_w, 3 * HD,
            fus_, HD, LoH, zzero(), NBAT,
            attn_b, 1, nullptr, 0, nullptr, 0);
    }

    // ===== Stage E: self attention =====
    {
        ZOffs z0o = zzero();
        rowdot_kernel<<<dim3(LO, NBAT), 256>>>(fus_, z0o, NBAT, LoH, HD, sw2, kl_, LO, HD);

        tgemm_kernel<<<dim3(LO / BN, LO / BM, 32), 256>>>(
            HD, fus_, HD, LoH, zzero(), fus_, HD, LoH, zzero(),
            S_, LO, (long long)LO * LO, zzero(), NBAT, sw3);

        softmax_row_kernel<<<dim3(LO, NBAT), 256>>>(S_, LO, (long long)LO * LO, kl_, LO);

        nngemm_kernel<<<dim3(HD / BN, LO / BM, 32), 256>>>(
            LO, S_, LO, (long long)LO * LO, zzero(), fus_, HD, LoH, zzero(),
            sa_, HD, LoH, zzero(), NBAT);
    }

    // ===== Stage F: fusion2 = relu([f|sa|f*sa|f-sa] @ self_w^T + b) =====
    {
        SegArgs sga = {};
        sga.segs[0] = {fus_, nullptr, 0, 0, LoH, 0, 0, 0, 0, 0};
        sga.segs[1] = {sa_,  nullptr, 0, 0, LoH, 0, 0, 0, 0, 0};
        sga.segs[2] = {fus_, sa_, 0, 0, LoH, 0, 0, LoH, 1, 0};
        sga.segs[3] = {fus_, sa_, 0, 0, LoH, 0, 0, LoH, 2, 0};
        sga.nseg = 4;
        segk_kernel<<<dim3(HD / BN, LO / BM, 32), 256>>>(
            4 * HD, sga, self_w, 4 * HD,
            corr_, HD, LoH, zzero(), NBAT,
            self_b, 1, nullptr, 0, nullptr, 0);
    }

    // ===== Stage G =====
    maxreduce_kernel<<<dim3(HD / 256, NBAT), 256>>>(corr_, (float*)d_out);
}

// round 8
// speedup vs baseline: 2.4129x; 1.0015x over previous
#include <cuda_runtime.h>
#include <cuda_fp16.h>
#include <math.h>
#include <stdint.h>

#define HD   1024
#define SEQ  1024
#define LO   256
#define LDOC 768
#define NBAT 32
#define NBZ  8
#define NL   4

// ---------------- device scratch ----------------
__device__ float g_S   [96 * LO * LO];
__device__ float g_kq  [NBAT * LO * LDOC];
__device__ float g_att [96 * LO * HD];
__device__ float g_corr[NBAT * LO * HD];
__device__ float g_opt [NBAT * LO * HD];
__device__ float g_a   [NBAT * LO * HD];
__device__ float g_co  [NBAT * LO * HD];
__device__ float g_fus [NBAT * LO * HD];
__device__ float g_sa  [NBAT * LO * HD];
__device__ float g_cow [NBAT * LO * LO];
__device__ float g_kl  [96 * LO];
__device__ float g_ql  [NBAT * LO];

struct ZOffs { long long o[12]; };

struct Seg {
    const float* A;
    const float* A2;
    long long c0, c1, s0;
    long long ac0, ac1, as0;
    int amode;                // 0 none, 1 mul, 2 sub
    int pad;
};
struct SegArgs { Seg segs[8]; int nseg; };

// ---------------- helpers ----------------
__device__ __forceinline__ unsigned ph2(float lo, float hi) {
    __half2 h = __floats2half2_rn(lo, hi);
    return *reinterpret_cast<unsigned*>(&h);
}

__device__ __forceinline__ void ldsm_x4_trans(unsigned& r0, unsigned& r1, unsigned& r2, unsigned& r3,
                                              uint32_t addr) {
    asm volatile("ldmatrix.sync.aligned.m8n8.x4.trans.shared.b16 {%0,%1,%2,%3}, [%4];"
                 : "=r"(r0), "=r"(r1), "=r"(r2), "=r"(r3) : "r"(addr));
}

__device__ __forceinline__ float blockReduceMax(float v, float* sm) {
    #pragma unroll
    for (int o = 16; o; o >>= 1) v = fmaxf(v, __shfl_xor_sync(0xffffffffu, v, o));
    int w = threadIdx.x >> 5;
    if ((threadIdx.x & 31) == 0) sm[w] = v;
    __syncthreads();
    if (threadIdx.x < 32) {
        v = (threadIdx.x < (blockDim.x >> 5)) ? sm[threadIdx.x] : -3.4e38f;
        #pragma unroll
        for (int o = 4; o; o >>= 1) v = fmaxf(v, __shfl_xor_sync(0xffffffffu, v, o));
        if (threadIdx.x == 0) sm[0] = v;
    }
    __syncthreads();
    v = sm[0];
    __syncthreads();
    return v;
}

__device__ __forceinline__ float blockReduceSum(float v, float* sm) {
    #pragma unroll
    for (int o = 16; o; o >>= 1) v += __shfl_xor_sync(0xffffffffu, v, o);
    int w = threadIdx.x >> 5;
    if ((threadIdx.x & 31) == 0) sm[w] = v;
    __syncthreads();
    if (threadIdx.x < 32) {
        v = (threadIdx.x < (blockDim.x >> 5)) ? sm[threadIdx.x] : 0.0f;
        #pragma unroll
        for (int o = 4; o; o >>= 1) v += __shfl_xor_sync(0xffffffffu, v, o);
        if (threadIdx.x == 0) sm[0] = v;
    }
    __syncthreads();
    v = sm[0];
    __syncthreads();
    return v;
}

#define BM 128
#define BN 128
#define ASTR 20            // u32 pitch of NT-format fp16 tiles (32 halves + pad)
#define BNNP 68            // u32 pitch of NN-format fp16 B tile rows (128 halves = 64 u32 + pad)

// ======== fp16 NT fragment compute: 8 warps 2x4, 64x32 warp tile, k16 per mma ======
#define NT16_COMPUTE_STAGE(Au, Bu)                                                   \
    _Pragma("unroll")                                                                \
    for (int kk = 0; kk < 2; ++kk) {                                                 \
        unsigned af[4][4], bf[4][2];                                                 \
        _Pragma("unroll")                                                            \
        for (int mt = 0; mt < 4; ++mt) {                                             \
            const int r0 = (warpM * 64 + mt * 16 + g) * ASTR + kk * 8 + c;           \
            af[mt][0] = Au[r0];                                                      \
            af[mt][1] = Au[r0 + 8 * ASTR];                                           \
            af[mt][2] = Au[r0 + 4];                                                  \
            af[mt][3] = Au[r0 + 8 * ASTR + 4];                                       \
        }                                                                            \
        _Pragma("unroll")                                                            \
        for (int nt = 0; nt < 4; ++nt) {                                             \
            const int n0 = warpN * 32 + nt * 8 + g;                                  \
            bf[nt][0] = Bu[n0 * ASTR + kk * 8 + c];                                  \
            bf[nt][1] = Bu[n0 * ASTR + kk * 8 + c + 4];                              \
        }                                                                            \
        _Pragma("unroll")                                                            \
        for (int mt = 0; mt < 4; ++mt)                                               \
            _Pragma("unroll")                                                        \
            for (int nt = 0; nt < 4; ++nt) {                                         \
                asm volatile(                                                        \
                    "mma.sync.aligned.m16n8k16.row.col.f32.f16.f16.f32 "             \
                    "{%0,%1,%2,%3}, {%4,%5,%6,%7}, {%8,%9}, {%0,%1,%2,%3};"          \
                    : "+f"(cfr[mt][nt][0]), "+f"(cfr[mt][nt][1]),                    \
                      "+f"(cfr[mt][nt][2]), "+f"(cfr[mt][nt][3])                     \
                    : "r"(af[mt][0]), "r"(af[mt][1]), "r"(af[mt][2]), "r"(af[mt][3]),\
                      "r"(bf[nt][0]), "r"(bf[nt][1]));                               \
            }                                                                        \
    }

// ================= fp16 NT GEMM: C = A @ B^T (S-matrices, cow) ======================
__global__ __launch_bounds__(256, 2)
void tgemm_kernel(int K,
                  const float* __restrict__ A, int lda, long long sA0, ZOffs aoffs,
                  const float* __restrict__ B, int ldb, long long sB0, ZOffs boffs,
                  float* __restrict__ C, int ldc, long long sC0, ZOffs coffs,
                  int nz0, const float* __restrict__ ascale)
{
    __shared__ unsigned As[2][BM * ASTR];
    __shared__ unsigned Bs[2][BN * ASTR];

    const int z  = blockIdx.z;
    const int z1 = z / nz0;
    const int z0 = z - z1 * nz0;
    const float* Ab = A + aoffs.o[z1] + (long long)z0 * sA0;
    const float* Bb = B + boffs.o[z1] + (long long)z0 * sB0;
    float*       Cb = C + coffs.o[z1] + (long long)z0 * sC0;

    const int bm = blockIdx.y * BM;
    const int bn = blockIdx.x * BN;
    const int tid  = threadIdx.x;
    const int lane = tid & 31;
    const int warp = tid >> 5;
    const int warpM = warp >> 2;
    const int warpN = warp & 3;
    const int g = lane >> 2;
    const int c = lane & 3;

    const int arow = tid >> 2;
    const int ac4  = tid & 3;

    uint4 au0, au1, bu0, bu1;

    float cfr[4][4][4];
    #pragma unroll
    for (int mt = 0; mt < 4; ++mt)
        #pragma unroll
        for (int nt = 0; nt < 4; ++nt)
            #pragma unroll
            for (int r = 0; r < 4; ++r) cfr[mt][nt][r] = 0.0f;

    auto ldg_stage = [&](int k0) {
        const int ke = k0 + ac4 * 8;
        float4 x0 = *reinterpret_cast<const float4*>(Ab + (long long)(bm + arow) * lda + ke);
        float4 x1 = *reinterpret_cast<const float4*>(Ab + (long long)(bm + arow) * lda + ke + 4);
        float4 y0 = *reinterpret_cast<const float4*>(Ab + (long long)(bm + arow + 64) * lda + ke);
        float4 y1 = *reinterpret_cast<const float4*>(Ab + (long long)(bm + arow + 64) * lda + ke + 4);
        if (ascale) {
            float s0 = ascale[ke + 0], s1 = ascale[ke + 1], s2 = ascale[ke + 2], s3 = ascale[ke + 3];
            float s4 = ascale[ke + 4], s5 = ascale[ke + 5], s6 = ascale[ke + 6], s7 = ascale[ke + 7];
            x0.x *= s0; x0.y *= s1; x0.z *= s2; x0.w *= s3;
            x1.x *= s4; x1.y *= s5; x1.z *= s6; x1.w *= s7;
            y0.x *= s0; y0.y *= s1; y0.z *= s2; y0.w *= s3;
            y1.x *= s4; y1.y *= s5; y1.z *= s6; y1.w *= s7;
        }
        au0 = make_uint4(ph2(x0.x, x0.y), ph2(x0.z, x0.w), ph2(x1.x, x1.y), ph2(x1.z, x1.w));
        au1 = make_uint4(ph2(y0.x, y0.y), ph2(y0.z, y0.w), ph2(y1.x, y1.y), ph2(y1.z, y1.w));
        float4 p0 = *reinterpret_cast<const float4*>(Bb + (long long)(bn + arow) * ldb + ke);
        float4 p1 = *reinterpret_cast<const float4*>(Bb + (long long)(bn + arow) * ldb + ke + 4);
        float4 q0 = *reinterpret_cast<const float4*>(Bb + (long long)(bn + arow + 64) * ldb + ke);
        float4 q1 = *reinterpret_cast<const float4*>(Bb + (long long)(bn + arow + 64) * ldb + ke + 4);
        bu0 = make_uint4(ph2(p0.x, p0.y), ph2(p0.z, p0.w), ph2(p1.x, p1.y), ph2(p1.z, p1.w));
        bu1 = make_uint4(ph2(q0.x, q0.y), ph2(q0.z, q0.w), ph2(q1.x, q1.y), ph2(q1.z, q1.w));
    };

    auto sts_stage = [&](int buf) {
        *reinterpret_cast<uint4*>(&As[buf][arow * ASTR + ac4 * 4]) = au0;
        *reinterpret_cast<uint4*>(&As[buf][(arow + 64) * ASTR + ac4 * 4]) = au1;
        *reinterpret_cast<uint4*>(&Bs[buf][arow * ASTR + ac4 * 4]) = bu0;
        *reinterpret_cast<uint4*>(&Bs[buf][(arow + 64) * ASTR + ac4 * 4]) = bu1;
    };

    int buf = 0;
    ldg_stage(0);
    sts_stage(0);
    __syncthreads();
    for (int k0 = 32; k0 < K; k0 += 32) {
        ldg_stage(k0);
        {
            const unsigned* Au = As[buf];
            const unsigned* Bu = Bs[buf];
            NT16_COMPUTE_STAGE(Au, Bu)
        }
        sts_stage(buf ^ 1);
        __syncthreads();
        buf ^= 1;
    }
    {
        const unsigned* Au = As[buf];
        const unsigned* Bu = Bs[buf];
        NT16_COMPUTE_STAGE(Au, Bu)
    }

    #pragma unroll
    for (int mt = 0; mt < 4; ++mt) {
        const int row = bm + warpM * 64 + mt * 16 + g;
        #pragma unroll
        for (int nt = 0; nt < 4; ++nt) {
            const int col = bn + warpN * 32 + nt * 8 + c * 2;
            #pragma unroll
            for (int half = 0; half < 2; ++half) {
                float* p = Cb + (long long)(row + half * 8) * ldc + col;
                p[0] = cfr[mt][nt][half * 2 + 0];
                p[1] = cfr[mt][nt][half * 2 + 1];
            }
        }
    }
}

// ================= fp16 segmented-K NT GEMM (concat in K, fused epilogue) ===========
__global__ __launch_bounds__(256, 2)
void segk_kernel(int Ktot, SegArgs sga,
                 const float* __restrict__ B, int ldb,
                 float* __restrict__ C, int ldc, long long sC0, ZOffs coffs, int nz0,
                 const float* __restrict__ bias, int act,
                 const float* __restrict__ e1, long long e1s,
                 const float* __restrict__ e2, long long e2s)
{
    __shared__ unsigned As[2][BM * ASTR];
    __shared__ unsigned Bs[2][BN * ASTR];

    const int z  = blockIdx.z;
    const int z1 = z / nz0;
    const int z0 = z - z1 * nz0;
    float* Cb = C + coffs.o[z1] + (long long)z0 * sC0;

    const int bm = blockIdx.y * BM;
    const int bn = blockIdx.x * BN;
    const int tid  = threadIdx.x;
    const int lane = tid & 31;
    const int warp = tid >> 5;
    const int warpM = warp >> 2;
    const int warpN = warp & 3;
    const int g = lane >> 2;
    const int c = lane & 3;

    const int arow = tid >> 2;
    const int ac4  = tid & 3;

    int curseg = -1;
    const float* Ab = nullptr;
    const float* A2b = nullptr;
    int am = 0;

    uint4 au0, au1, bu0, bu1;

    float cfr[4][4][4];
    #pragma unroll
    for (int mt = 0; mt < 4; ++mt)
        #pragma unroll
        for (int nt = 0; nt < 4; ++nt)
            #pragma unroll
            for (int r = 0; r < 4; ++r) cfr[mt][nt][r] = 0.0f;

    auto ldg_stage = [&](int k0) {
        const int s = k0 >> 10;
        if (s != curseg) {
            curseg = s;
            const Seg& sg = sga.segs[s];
            Ab = sg.A + sg.c0 + sg.c1 * z1 + sg.s0 * z0;
            am = sg.amode;
            A2b = am ? (sg.A2 + sg.ac0 + sg.ac1 * z1 + sg.as0 * z0) : nullptr;
        }
        const int kl = (k0 & 1023) + ac4 * 8;
        float4 x0 = *reinterpret_cast<const float4*>(Ab + (long long)(bm + arow) * 1024 + kl);
        float4 x1 = *reinterpret_cast<const float4*>(Ab + (long long)(bm + arow) * 1024 + kl + 4);
        float4 y0 = *reinterpret_cast<const float4*>(Ab + (long long)(bm + arow + 64) * 1024 + kl);
        float4 y1 = *reinterpret_cast<const float4*>(Ab + (long long)(bm + arow + 64) * 1024 + kl + 4);
        if (am) {
            float4 u0 = *reinterpret_cast<const float4*>(A2b + (long long)(bm + arow) * 1024 + kl);
            float4 u1 = *reinterpret_cast<const float4*>(A2b + (long long)(bm + arow) * 1024 + kl + 4);
            float4 v0 = *reinterpret_cast<const float4*>(A2b + (long long)(bm + arow + 64) * 1024 + kl);
            float4 v1 = *reinterpret_cast<const float4*>(A2b + (long long)(bm + arow + 64) * 1024 + kl + 4);
            if (am == 1) {
                x0.x *= u0.x; x0.y *= u0.y; x0.z *= u0.z; x0.w *= u0.w;
                x1.x *= u1.x; x1.y *= u1.y; x1.z *= u1.z; x1.w *= u1.w;
                y0.x *= v0.x; y0.y *= v0.y; y0.z *= v0.z; y0.w *= v0.w;
                y1.x *= v1.x; y1.y *= v1.y; y1.z *= v1.z; y1.w *= v1.w;
            } else {
                x0.x -= u0.x; x0.y -= u0.y; x0.z -= u0.z; x0.w -= u0.w;
                x1.x -= u1.x; x1.y -= u1.y; x1.z -= u1.z; x1.w -= u1.w;
                y0.x -= v0.x; y0.y -= v0.y; y0.z -= v0.z; y0.w -= v0.w;
                y1.x -= v1.x; y1.y -= v1.y; y1.z -= v1.z; y1.w -= v1.w;
            }
        }
        au0 = make_uint4(ph2(x0.x, x0.y), ph2(x0.z, x0.w), ph2(x1.x, x1.y), ph2(x1.z, x1.w));
        au1 = make_uint4(ph2(y0.x, y0.y), ph2(y0.z, y0.w), ph2(y1.x, y1.y), ph2(y1.z, y1.w));
        const int ke = k0 + ac4 * 8;
        float4 p0 = *reinterpret_cast<const float4*>(B + (long long)(bn + arow) * ldb + ke);
        float4 p1 = *reinterpret_cast<const float4*>(B + (long long)(bn + arow) * ldb + ke + 4);
        float4 q0 = *reinterpret_cast<const float4*>(B + (long long)(bn + arow + 64) * ldb + ke);
        float4 q1 = *reinterpret_cast<const float4*>(B + (long long)(bn + arow + 64) * ldb + ke + 4);
        bu0 = make_uint4(ph2(p0.x, p0.y), ph2(p0.z, p0.w), ph2(p1.x, p1.y), ph2(p1.z, p1.w));
        bu1 = make_uint4(ph2(q0.x, q0.y), ph2(q0.z, q0.w), ph2(q1.x, q1.y), ph2(q1.z, q1.w));
    };

    auto sts_stage = [&](int buf) {
        *reinterpret_cast<uint4*>(&As[buf][arow * ASTR + ac4 * 4]) = au0;
        *reinterpret_cast<uint4*>(&As[buf][(arow + 64) * ASTR + ac4 * 4]) = au1;
        *reinterpret_cast<uint4*>(&Bs[buf][arow * ASTR + ac4 * 4]) = bu0;
        *reinterpret_cast<uint4*>(&Bs[buf][(arow + 64) * ASTR + ac4 * 4]) = bu1;
    };

    int buf = 0;
    ldg_stage(0);
    sts_stage(0);
    __syncthreads();
    for (int k0 = 32; k0 < Ktot; k0 += 32) {
        ldg_stage(k0);
        {
            const unsigned* Au = As[buf];
            const unsigned* Bu = Bs[buf];
            NT16_COMPUTE_STAGE(Au, Bu)
        }
        sts_stage(buf ^ 1);
        __syncthreads();
        buf ^= 1;
    }
    {
        const unsigned* Au = As[buf];
        const unsigned* Bu = Bs[buf];
        NT16_COMPUTE_STAGE(Au, Bu)
    }

    #pragma unroll
    for (int mt = 0; mt < 4; ++mt) {
        const int row = bm + warpM * 64 + mt * 16 + g;
        #pragma unroll
        for (int nt = 0; nt < 4; ++nt) {
            const int col = bn + warpN * 32 + nt * 8 + c * 2;
            #pragma unroll
            for (int half = 0; half < 2; ++half) {
                const int r2 = row + half * 8;
                float* p = Cb + (long long)r2 * ldc + col;
                float v0 = cfr[mt][nt][half * 2 + 0];
                float v1 = cfr[mt][nt][half * 2 + 1];
                if (bias) { v0 += bias[col]; v1 += bias[col + 1]; }
                if (act == 1)      { v0 = fmaxf(v0, 0.0f); v1 = fmaxf(v1, 0.0f); }
                else if (act == 2) { v0 = tanhf(v0); v1 = tanhf(v1); }
                else if (act == 4) {
                    const float g0 = 1.0f / (1.0f + expf(-v0));
                    const float g1 = 1.0f / (1.0f + expf(-v1));
                    const float* pe = e1 + (long long)z0 * e1s + (long long)r2 * ldc + col;
                    const float* pc = e2 + (long long)z0 * e2s + (long long)r2 * ldc + col;
                    v0 = pe[0] * g0 + pc[0] * (1.0f - g0);
                    v1 = pe[1] * g1 + pc[1] * (1.0f - g1);
                }
                p[0] = v0; p[1] = v1;
            }
        }
    }
}

// ================= fp16 NN GEMM via ldmatrix.trans (P@V etc.) =======================
// A [M,K] fp32 row-major (k-major, NT-style tile); B [K,N] fp32 row-major ->
// fp16 smem tile [k][n] with pitch BNNP; B fragments via ldmatrix.x4.trans.
__global__ __launch_bounds__(256, 2)
void nngemm_kernel(int K,
                   const float* __restrict__ A, int lda, long long sA0, ZOffs aoffs,
                   const float* __restrict__ B, int ldb, long long sB0, ZOffs boffs,
                   float* __restrict__ C, int ldc, long long sC0, ZOffs coffs,
                   int nz0)
{
    __shared__ unsigned As[2][BM * ASTR];
    __shared__ unsigned Bs[2][32 * BNNP];

    const int z  = blockIdx.z;
    const int z1 = z / nz0;
    const int z0 = z - z1 * nz0;
    const float* Ab = A + aoffs.o[z1] + (long long)z0 * sA0;
    const float* Bb = B + boffs.o[z1] + (long long)z0 * sB0;
    float*       Cb = C + coffs.o[z1] + (long long)z0 * sC0;

    const int bm = blockIdx.y * BM;
    const int bn = blockIdx.x * BN;
    const int tid  = threadIdx.x;
    const int lane = tid & 31;
    const int warp = tid >> 5;
    const int warpM = warp >> 2;
    const int warpN = warp & 3;
    const int g = lane >> 2;
    const int c = lane & 3;

    const int arow = tid >> 2;
    const int ac4  = tid & 3;
    const int bkr  = tid >> 3;          // 0..31 B tile row
    const int bnc  = (tid & 7) * 16;    // B float col base

    // ldmatrix per-lane address component (bytes within a buffer):
    // row = kk*16 + (lane&15); col halves = warpN*32 + ntp*16 + ((lane>>4)*8)
    const uint32_t bs_base = (uint32_t)__cvta_generic_to_shared(&Bs[0][0]);
    const uint32_t lane_off = (uint32_t)(lane & 15) * (BNNP * 4) +
                              (uint32_t)(warpN * 32 + ((lane >> 4) << 3)) * 2;

    uint4 au0, au1, bu[2];

    float cfr[4][4][4];
    #pragma unroll
    for (int mt = 0; mt < 4; ++mt)
        #pragma unroll
        for (int nt = 0; nt < 4; ++nt)
            #pragma unroll
            for (int r = 0; r < 4; ++r) cfr[mt][nt][r] = 0.0f;

    auto ldg_stage = [&](int k0) {
        const int ke = k0 + ac4 * 8;
        float4 x0 = *reinterpret_cast<const float4*>(Ab + (long long)(bm + arow) * lda + ke);
        float4 x1 = *reinterpret_cast<const float4*>(Ab + (long long)(bm + arow) * lda + ke + 4);
        float4 y0 = *reinterpret_cast<const float4*>(Ab + (long long)(bm + arow + 64) * lda + ke);
        float4 y1 = *reinterpret_cast<const float4*>(Ab + (long long)(bm + arow + 64) * lda + ke + 4);
        au0 = make_uint4(ph2(x0.x, x0.y), ph2(x0.z, x0.w), ph2(x1.x, x1.y), ph2(x1.z, x1.w));
        au1 = make_uint4(ph2(y0.x, y0.y), ph2(y0.z, y0.w), ph2(y1.x, y1.y), ph2(y1.z, y1.w));
        const float* brow = Bb + (long long)(k0 + bkr) * ldb + bn + bnc;
        float4 p0 = *reinterpret_cast<const float4*>(brow);
        float4 p1 = *reinterpret_cast<const float4*>(brow + 4);
        float4 p2 = *reinterpret_cast<const float4*>(brow + 8);
        float4 p3 = *reinterpret_cast<const float4*>(brow + 12);
        bu[0] = make_uint4(ph2(p0.x, p0.y), ph2(p0.z, p0.w), ph2(p1.x, p1.y), ph2(p1.z, p1.w));
        bu[1] = make_uint4(ph2(p2.x, p2.y), ph2(p2.z, p2.w), ph2(p3.x, p3.y), ph2(p3.z, p3.w));
    };

    auto sts_stage = [&](int buf) {
        *reinterpret_cast<uint4*>(&As[buf][arow * ASTR + ac4 * 4]) = au0;
        *reinterpret_cast<uint4*>(&As[buf][(arow + 64) * ASTR + ac4 * 4]) = au1;
        unsigned* brow = &Bs[buf][bkr * BNNP + (tid & 7) * 8];
        *reinterpret_cast<uint4*>(brow)     = bu[0];
        *reinterpret_cast<uint4*>(brow + 4) = bu[1];
    };

    auto compute_stage = [&](int buf) {
        const unsigned* Au = As[buf];
        const uint32_t bbuf = bs_base + (uint32_t)buf * (32 * BNNP * 4) + lane_off;
        #pragma unroll
        for (int kk = 0; kk < 2; ++kk) {
            unsigned af[4][4], bf[4][2];
            #pragma unroll
            for (int mt = 0; mt < 4; ++mt) {
                const int r0 = (warpM * 64 + mt * 16 + g) * ASTR + kk * 8 + c;
                af[mt][0] = Au[r0];
                af[mt][1] = Au[r0 + 8 * ASTR];
                af[mt][2] = Au[r0 + 4];
                af[mt][3] = Au[r0 + 8 * ASTR + 4];
            }
            #pragma unroll
            for (int ntp = 0; ntp < 2; ++ntp) {
                const uint32_t addr = bbuf + (uint32_t)(kk * 16) * (BNNP * 4) + (uint32_t)(ntp * 32);
                ldsm_x4_trans(bf[2 * ntp][0], bf[2 * ntp][1], bf[2 * ntp + 1][0], bf[2 * ntp + 1][1], addr);
            }
            #pragma unroll
            for (int mt = 0; mt < 4; ++mt)
                #pragma unroll
                for (int nt = 0; nt < 4; ++nt) {
                    asm volatile(
                        "mma.sync.aligned.m16n8k16.row.col.f32.f16.f16.f32 "
                        "{%0,%1,%2,%3}, {%4,%5,%6,%7}, {%8,%9}, {%0,%1,%2,%3};"
                        : "+f"(cfr[mt][nt][0]), "+f"(cfr[mt][nt][1]),
                          "+f"(cfr[mt][nt][2]), "+f"(cfr[mt][nt][3])
                        : "r"(af[mt][0]), "r"(af[mt][1]), "r"(af[mt][2]), "r"(af[mt][3]),
                          "r"(bf[nt][0]), "r"(bf[nt][1]));
                }
        }
    };

    int buf = 0;
    ldg_stage(0);
    sts_stage(0);
    __syncthreads();
    for (int k0 = 32; k0 < K; k0 += 32) {
        ldg_stage(k0);
        compute_stage(buf);
        sts_stage(buf ^ 1);
        __syncthreads();
        buf ^= 1;
    }
    compute_stage(buf);

    #pragma unroll
    for (int mt = 0; mt < 4; ++mt) {
        const int row = bm + warpM * 64 + mt * 16 + g;
        #pragma unroll
        for (int nt = 0; nt < 4; ++nt) {
            const int col = bn + warpN * 32 + nt * 8 + c * 2;
            #pragma unroll
            for (int half = 0; half < 2; ++half) {
                float* p = Cb + (long long)(row + half * 8) * ldc + col;
                p[0] = cfr[mt][nt][half * 2 + 0];
                p[1] = cfr[mt][nt][half * 2 + 1];
            }
        }
    }
}

// ---------------- batched rowdot ----------------
__global__ void rowdot_kernel(const float* __restrict__ X, ZOffs offs, int nz0, long long s0,
                              int ld, const float* __restrict__ w, float* __restrict__ out,
                              int rows, int Kd)
{
    __shared__ float sm[32];
    const int r = blockIdx.x, z = blockIdx.y;
    const int z1 = z / nz0, z0 = z - z1 * nz0;
    const float* x = X + offs.o[z1] + (long long)z0 * s0 + (long long)r * ld;
    float s = 0.0f;
    for (int k = threadIdx.x; k < Kd; k += 256) s += x[k] * w[k];
    s = blockReduceSum(s, sm);
    if (threadIdx.x == 0) out[(long long)z * rows + r] = s;
}

// ---------------- row softmax in-place (kl indexed via offset table) ----------------
__global__ void softmax_row_kernel(float* __restrict__ S, int ldS, long long strideS,
                                   const float* __restrict__ kl, ZOffs klo, long long kls0,
                                   int nz0, int Lk)
{
    __shared__ float sm[32];
    const int q = blockIdx.x, z = blockIdx.y;
    const int z1 = z / nz0, z0 = z - z1 * nz0;
    float* row = S + (long long)z * strideS + (long long)q * ldS;
    const float* klb = kl + klo.o[z1] + (long long)z0 * kls0;

    float v[3];
    int n = 0;
    float m = -3.4e38f;
    for (int k = threadIdx.x; k < Lk; k += 256) {
        float x = row[k] + klb[k];
        v[n++] = x;
        m = fmaxf(m, x);
    }
    m = blockReduceMax(m, sm);
    float s = 0.0f;
    for (int t = 0; t < n; ++t) { v[t] = expf(v[t] - m); s += v[t]; }
    s = blockReduceSum(s, sm);
    const float inv = 1.0f / s;
    n = 0;
    for (int k = threadIdx.x; k < Lk; k += 256) row[k] = v[n++] * inv;
}

// ---------------- column softmax ----------------
__global__ void softmax_col_kernel(const float* __restrict__ S, float* __restrict__ kq,
                                   const float* __restrict__ ql)
{
    const int x = threadIdx.x & 31;
    const int y = threadIdx.x >> 5;
    const int col = blockIdx.x * 32 + x;
    const int z = blockIdx.y;
    const float* Sb = S + (long long)z * (LO * LDOC);
    const float* qlb = ql + (long long)z * LO;

    float vals[LO / 8];
    float m = -3.4e38f;
    #pragma unroll 4
    for (int it = 0; it < LO / 8; ++it) {
        const int r = it * 8 + y;
        float v = qlb[r] + Sb[(long long)r * LDOC + col];
        vals[it] = v;
        m = fmaxf(m, v);
    }
    __shared__ float red[8][32];
    red[y][x] = m;
    __syncthreads();
    if (y == 0) {
        float mm = red[0][x];
        #pragma unroll
        for (int t = 1; t < 8; ++t) mm = fmaxf(mm, red[t][x]);
        red[0][x] = mm;
    }
    __syncthreads();
    m = red[0][x];
    __syncthreads();

    float s = 0.0f;
    #pragma unroll 4
    for (int it = 0; it < LO / 8; ++it) { vals[it] = expf(vals[it] - m); s += vals[it]; }
    red[y][x] = s;
    __syncthreads();
    if (y == 0) {
        float ss = 0.0f;
        #pragma unroll
        for (int t = 0; t < 8; ++t) ss += red[t][x];
        red[0][x] = ss;
    }
    __syncthreads();
    const float inv = 1.0f / red[0][x];

    float* kqb = kq + (long long)z * (LO * LDOC);
    #pragma unroll 4
    for (int it = 0; it < LO / 8; ++it)
        kqb[(long long)(it * 8 + y) * LDOC + col] = vals[it] * inv;
}

// ---------------- final max over positions ----------------
__global__ void maxreduce_kernel(const float* __restrict__ f, float* __restrict__ out)
{
    const int h = blockIdx.x * 256 + threadIdx.x;
    const int b = blockIdx.y;
    float m = -3.4e38f;
    const float* base = f + (long long)b * LO * HD + h;
    #pragma unroll 8
    for (int r = 0; r < LO; ++r) m = fmaxf(m, base[(long long)r * HD]);
    out[(long long)b * HD + h] = m;
}

// ---------------- host ----------------
static ZOffs zzero() { ZOffs z; for (int i = 0; i < 12; ++i) z.o[i] = 0; return z; }

extern "C" void kernel_launch(void* const* d_in, const int* in_sizes, int n_in,
                              void* d_out, int out_size)
{
    const float* last   = (const float*)d_in[4];
    const float* ow2    = (const float*)d_in[6];
    const float* ow3    = (const float*)d_in[7];
    const float* dw1    = (const float*)d_in[8];
    const float* dw2    = (const float*)d_in[9];
    const float* dw3    = (const float*)d_in[10];
    const float* sw2    = (const float*)d_in[12];
    const float* sw3    = (const float*)d_in[13];
    const float* comp_w = (const float*)d_in[14];
    const float* comp_b = (const float*)d_in[15];
    const float* gate_w = (const float*)d_in[16];
    const float* gate_b = (const float*)d_in[17];
    const float* attn_w = (const float*)d_in[18];
    const float* attn_b = (const float*)d_in[19];
    const float* self_w = (const float*)d_in[20];
    const float* self_b = (const float*)d_in[21];

    float *S_, *kq_, *att_, *corr_, *opt_, *a_, *co_, *fus_, *sa_, *cow_, *kl_, *ql_;
    cudaGetSymbolAddress((void**)&S_,   g_S);
    cudaGetSymbolAddress((void**)&kq_,  g_kq);
    cudaGetSymbolAddress((void**)&att_, g_att);
    cudaGetSymbolAddress((void**)&corr_,g_corr);
    cudaGetSymbolAddress((void**)&opt_, g_opt);
    cudaGetSymbolAddress((void**)&a_,   g_a);
    cudaGetSymbolAddress((void**)&co_,  g_co);
    cudaGetSymbolAddress((void**)&fus_, g_fus);
    cudaGetSymbolAddress((void**)&sa_,  g_sa);
    cudaGetSymbolAddress((void**)&cow_, g_cow);
    cudaGetSymbolAddress((void**)&kl_,  g_kl);
    cudaGetSymbolAddress((void**)&ql_,  g_ql);

    const long long sSeq = (long long)SEQ * HD;
    const long long sQ   = 4LL * SEQ * HD;
    const long long LoH  = (long long)LO * HD;

    long long curoff[NL], kvoff[12], attoff[12];
    int jv[12];
    for (int i = 0; i < NL; ++i) curoff[i] = ((long long)i * SEQ + LDOC) * HD;
    for (int i = 0, p = 0; i < NL; ++i)
        for (int j = 0; j < NL; ++j) {
            if (j == i) continue;
            kvoff[p] = ((long long)j * SEQ + LDOC) * HD;
            attoff[p] = (long long)p * NBZ * LoH;
            jv[p] = j;
            ++p;
        }

    // ===== Stage A: 12 pair attentions =====
    {
        // kl for 4 labels x 8 batch (deduped)
        ZOffs lblo = zzero();
        for (int j = 0; j < NL; ++j) lblo.o[j] = ((long long)j * SEQ + LDOC) * HD;
        rowdot_kernel<<<dim3(LO, NL * NBZ), 256>>>(last, lblo, NBZ, sQ, HD, ow2, kl_, LO, HD);

        ZOffs kvo = zzero(), ao = zzero(), co = zzero();
        for (int p = 0; p < 12; ++p) {
            kvo.o[p] = kvoff[p];
            ao.o[p] = curoff[p / 3];
            co.o[p] = (long long)p * NBZ * LO * LO;
        }
        tgemm_kernel<<<dim3(LO / BN, LO / BM, 96), 256>>>(
            HD, last, HD, sQ, ao, last, HD, sQ, kvo,
            S_, LO, (long long)LO * LO, co, NBZ, ow3);

        ZOffs klo = zzero();
        for (int p = 0; p < 12; ++p) klo.o[p] = (long long)jv[p] * NBZ * LO;
        softmax_row_kernel<<<dim3(LO, 96), 256>>>(S_, LO, (long long)LO * LO, kl_, klo, LO, NBZ, LO);

        ZOffs so = co, ato = zzero();
        for (int p = 0; p < 12; ++p) ato.o[p] = attoff[p];
        nngemm_kernel<<<dim3(HD / BN, LO / BM, 96), 256>>>(
            LO, S_, LO, (long long)LO * LO, so, last, HD, sQ, kvo,
            att_, HD, LoH, ato, NBZ);
    }

    // ===== comp: single segmented GEMM, K = 7*1024 =====
    {
        SegArgs sga = {};
        sga.segs[0] = {last, nullptr, (long long)LDOC * HD, (long long)SEQ * HD, sQ, 0, 0, 0, 0, 0};
        for (int m = 0; m < 3; ++m) {
            Seg mulseg = {last, att_, (long long)LDOC * HD, (long long)SEQ * HD, sQ,
                          (long long)m * NBZ * LoH, 3LL * NBZ * LoH, LoH, 1, 0};
            Seg subseg = mulseg; subseg.amode = 2;
            sga.segs[1 + 2 * m] = mulseg;
            sga.segs[2 + 2 * m] = subseg;
        }
        sga.nseg = 7;
        ZOffs co = zzero();
        for (int i = 0; i < NL; ++i) co.o[i] = (long long)i * LoH;
        segk_kernel<<<dim3(HD / BN, LO / BM, 32), 256>>>(
            7 * HD, sga, comp_w, 7 * HD,
            corr_, HD, 4 * LoH, co, NBZ,
            comp_b, 2, nullptr, 0, nullptr, 0);
    }

    // ===== Stage B: gate GEMM with fused blend -> opt =====
    {
        SegArgs sga = {};
        sga.segs[0] = {last, nullptr, (long long)LDOC * HD, 0, sSeq, 0, 0, 0, 0, 0};
        sga.segs[1] = {corr_, nullptr, 0, 0, LoH, 0, 0, 0, 0, 0};
        sga.nseg = 2;
        segk_kernel<<<dim3(HD / BN, LO / BM, 32), 256>>>(
            2 * HD, sga, gate_w, 2 * HD,
            opt_, HD, LoH, zzero(), NBAT,
            gate_b, 4, last + (long long)LDOC * HD, sSeq, corr_, LoH);
    }

    // ===== Stage C: doc attention =====
    {
        ZOffs z0o = zzero();
        rowdot_kernel<<<dim3(LO, NBAT), 256>>>(opt_, z0o, NBAT, LoH, HD, dw1, ql_, LO, HD);
        rowdot_kernel<<<dim3(LDOC, NBAT), 256>>>(last, z0o, NBAT, sSeq, HD, dw2, kl_, LDOC, HD);

        tgemm_kernel<<<dim3(LDOC / BN, LO / BM, 32), 256>>>(
            HD, opt_, HD, LoH, zzero(), last, HD, sSeq, zzero(),
            S_, LDOC, (long long)LO * LDOC, zzero(), NBAT, dw3);

        softmax_col_kernel<<<dim3(LDOC / 32, NBAT), 256>>>(S_, kq_, ql_);
        softmax_row_kernel<<<dim3(LO, NBAT), 256>>>(S_, LDOC, (long long)LO * LDOC, kl_, zzero(), LDOC, NBAT, LDOC);

        nngemm_kernel<<<dim3(HD / BN, LO / BM, 32), 256>>>(
            LDOC, S_, LDOC, (long long)LO * LDOC, zzero(), last, HD, sSeq, zzero(),
            a_, HD, LoH, zzero(), NBAT);

        tgemm_kernel<<<dim3(LO / BN, LO / BM, 32), 256>>>(
            LDOC, S_, LDOC, (long long)LO * LDOC, zzero(), kq_, LDOC, (long long)LO * LDOC, zzero(),
            cow_, LO, (long long)LO * LO, zzero(), NBAT, nullptr);

        nngemm_kernel<<<dim3(HD / BN, LO / BM, 32), 256>>>(
            LO, cow_, LO, (long long)LO * LO, zzero(), opt_, HD, LoH, zzero(),
            co_, HD, LoH, zzero(), NBAT);
    }

    // ===== Stage D: fusion = relu([opt|a|co] @ attn_w^T + b) =====
    {
        SegArgs sga = {};
        sga.segs[0] = {opt_, nullptr, 0, 0, LoH, 0, 0, 0, 0, 0};
        sga.segs[1] = {a_,   nullptr, 0, 0, LoH, 0, 0, 0, 0, 0};
        sga.segs[2] = {co_,  nullptr, 0, 0, LoH, 0, 0, 0, 0, 0};
        sga.nseg = 3;
        segk_kernel<<<dim3(HD / BN, LO / BM, 32), 256>>>(
            3 * HD, sga, attn_w, 3 * HD,
            fus_, HD, LoH, zzero(), NBAT,
            attn_b, 1, nullptr, 0, nullptr, 0);
    }

    // ===== Stage E: self attention =====
    {
        ZOffs z0o = zzero();
        rowdot_kernel<<<dim3(LO, NBAT), 256>>>(fus_, z0o, NBAT, LoH, HD, sw2, kl_, LO, HD);

        tgemm_kernel<<<dim3(LO / BN, LO / BM, 32), 256>>>(
            HD, fus_, HD, LoH, zzero(), fus_, HD, LoH, zzero(),
            S_, LO, (long long)LO * LO, zzero(), NBAT, sw3);

        softmax_row_kernel<<<dim3(LO, NBAT), 256>>>(S_, LO, (long long)LO * LO, kl_, zzero(), LO, NBAT, LO);

        nngemm_kernel<<<dim3(HD / BN, LO / BM, 32), 256>>>(
            LO, S_, LO, (long long)LO * LO, zzero(), fus_, HD, LoH, zzero(),
            sa_, HD, LoH, zzero(), NBAT);
    }

    // ===== Stage F: fusion2 = relu([f|sa|f*sa|f-sa] @ self_w^T + b) =====
    {
        SegArgs sga = {};
        sga.segs[0] = {fus_, nullptr, 0, 0, LoH, 0, 0, 0, 0, 0};
        sga.segs[1] = {sa_,  nullptr, 0, 0, LoH, 0, 0, 0, 0, 0};
        sga.segs[2] = {fus_, sa_, 0, 0, LoH, 0, 0, LoH, 1, 0};
        sga.segs[3] = {fus_, sa_, 0, 0, LoH, 0, 0, LoH, 2, 0};
        sga.nseg = 4;
        segk_kernel<<<dim3(HD / BN, LO / BM, 32), 256>>>(
            4 * HD, sga, self_w, 4 * HD,
            corr_, HD, LoH, zzero(), NBAT,
            self_b, 1, nullptr, 0, nullptr, 0);
    }

    // ===== Stage G =====
    maxreduce_kernel<<<dim3(HD / 256, NBAT), 256>>>(corr_, (float*)d_out);
}

// round 9
// speedup vs baseline: 2.7629x; 1.1450x over previous
#include <cuda_runtime.h>
#include <cuda_fp16.h>
#include <math.h>
#include <stdint.h>

#define HD   1024
#define SEQ  1024
#define LO   256
#define LDOC 768
#define NBAT 32
#define NBZ  8
#define NL   4

// ---------------- fp32 scratch ----------------
__device__ float g_S [96 * LO * LO];        // logits (stage A 96xLOxLO; doc 32xLOxLDOC; self 32xLOxLO)
__device__ float g_kl[NBAT * LDOC];
__device__ float g_ql[NBAT * LO];

// ---------------- fp16 buffers ----------------
__device__ __half h_last [NBAT * SEQ * HD];
__device__ __half h_att  [96 * LO * HD];
__device__ __half h_mul  [96 * LO * HD];
__device__ __half h_sub  [96 * LO * HD];
__device__ __half h_P    [96 * LO * LO];     // also doc P (32*LO*LDOC, same size)
__device__ __half h_kq   [NBAT * LO * LDOC];
__device__ __half h_cow  [NBAT * LO * LO];
__device__ __half h_corr [NBAT * LO * HD];
__device__ __half h_opt  [NBAT * LO * HD];
__device__ __half h_a    [NBAT * LO * HD];
__device__ __half h_co   [NBAT * LO * HD];
__device__ __half h_fus  [NBAT * LO * HD];
__device__ __half h_sa   [NBAT * LO * HD];
__device__ __half h_fm   [NBAT * LO * HD];
__device__ __half h_fs   [NBAT * LO * HD];
__device__ __half h_compw[7 * HD * HD];
__device__ __half h_gatew[2 * HD * HD];
__device__ __half h_attnw[3 * HD * HD];
__device__ __half h_selfw[4 * HD * HD];

struct ZOffs { long long o[12]; };
struct HSeg  { const __half* A; long long c0, c1, s0; };
struct HSegArgs { HSeg segs[8]; int nseg; };

// ---------------- helpers ----------------
__device__ __forceinline__ void cpa16(uint32_t dst, const void* src) {
    asm volatile("cp.async.cg.shared.global [%0], [%1], 16;" :: "r"(dst), "l"(src));
}
#define CP_COMMIT() asm volatile("cp.async.commit_group;" ::: "memory")
#define CP_WAIT2()  asm volatile("cp.async.wait_group 2;" ::: "memory")

__device__ __forceinline__ unsigned hmul2u(unsigned a, __half2 s) {
    __half2 x = *reinterpret_cast<__half2*>(&a);
    x = __hmul2(x, s);
    return *reinterpret_cast<unsigned*>(&x);
}

__device__ __forceinline__ void ldsm_x4_trans(unsigned& r0, unsigned& r1, unsigned& r2, unsigned& r3,
                                              uint32_t addr) {
    asm volatile("ldmatrix.sync.aligned.m8n8.x4.trans.shared.b16 {%0,%1,%2,%3}, [%4];"
                 : "=r"(r0), "=r"(r1), "=r"(r2), "=r"(r3) : "r"(addr));
}

__device__ __forceinline__ float blockReduceMax(float v, float* sm) {
    #pragma unroll
    for (int o = 16; o; o >>= 1) v = fmaxf(v, __shfl_xor_sync(0xffffffffu, v, o));
    int w = threadIdx.x >> 5;
    if ((threadIdx.x & 31) == 0) sm[w] = v;
    __syncthreads();
    if (threadIdx.x < 32) {
        v = (threadIdx.x < (blockDim.x >> 5)) ? sm[threadIdx.x] : -3.4e38f;
        #pragma unroll
        for (int o = 4; o; o >>= 1) v = fmaxf(v, __shfl_xor_sync(0xffffffffu, v, o));
        if (threadIdx.x == 0) sm[0] = v;
    }
    __syncthreads();
    v = sm[0];
    __syncthreads();
    return v;
}

__device__ __forceinline__ float blockReduceSum(float v, float* sm) {
    #pragma unroll
    for (int o = 16; o; o >>= 1) v += __shfl_xor_sync(0xffffffffu, v, o);
    int w = threadIdx.x >> 5;
    if ((threadIdx.x & 31) == 0) sm[w] = v;
    __syncthreads();
    if (threadIdx.x < 32) {
        v = (threadIdx.x < (blockDim.x >> 5)) ? sm[threadIdx.x] : 0.0f;
        #pragma unroll
        for (int o = 4; o; o >>= 1) v += __shfl_xor_sync(0xffffffffu, v, o);
        if (threadIdx.x == 0) sm[0] = v;
    }
    __syncthreads();
    v = sm[0];
    __syncthreads();
    return v;
}

#define BM 128
#define BN 128
#define ASTR 20            // u32 pitch per tile row (32 halves in 16 u32 + pad)
#define STG 2560           // u32 per stage tile (128*20)
#define BOFF 10240         // NT: B stages start (4*STG)
#define BNNP 68            // NN B row pitch (u32)
#define NNSTG 2176         // 32*BNNP
#define NT_SMEM 81920
#define NN_SMEM 75776

// fragment index helpers usable in all kernels
#define NT16_LOAD_A(Au)                                                  \
    _Pragma("unroll")                                                    \
    for (int mt = 0; mt < 4; ++mt) {                                     \
        const int r0 = (warpM * 64 + mt * 16 + g) * ASTR + kk * 8 + c;   \
        af[mt][0] = Au[r0];                                              \
        af[mt][1] = Au[r0 + 8 * ASTR];                                   \
        af[mt][2] = Au[r0 + 4];                                          \
        af[mt][3] = Au[r0 + 8 * ASTR + 4];                               \
    }

#define NT16_MMA()                                                                   \
    _Pragma("unroll")                                                                \
    for (int mt = 0; mt < 4; ++mt)                                                   \
        _Pragma("unroll")                                                            \
        for (int nt = 0; nt < 4; ++nt) {                                             \
            asm volatile(                                                            \
                "mma.sync.aligned.m16n8k16.row.col.f32.f16.f16.f32 "                 \
                "{%0,%1,%2,%3}, {%4,%5,%6,%7}, {%8,%9}, {%0,%1,%2,%3};"              \
                : "+f"(cfr[mt][nt][0]), "+f"(cfr[mt][nt][1]),                        \
                  "+f"(cfr[mt][nt][2]), "+f"(cfr[mt][nt][3])                         \
                : "r"(af[mt][0]), "r"(af[mt][1]), "r"(af[mt][2]), "r"(af[mt][3]),    \
                  "r"(bf[nt][0]), "r"(bf[nt][1]));                                   \
        }

// ================= fp16 NT GEMM (cp.async 4-stage): C = A @ B^T =====================
// OUT16: 0 -> fp32 C, 1 -> fp16 C. Optional bscale (fp32 per-k) applied to B frags.
template <int OUT16>
__global__ __launch_bounds__(256)
void tgemm_kernel(int K,
                  const __half* __restrict__ A, int lda, long long sA0, ZOffs aoffs,
                  const __half* __restrict__ B, int ldb, long long sB0, ZOffs boffs,
                  void* __restrict__ Cv, int ldc, long long sC0, ZOffs coffs,
                  int nz0, const float* __restrict__ bscale)
{
    extern __shared__ unsigned dsm[];
    const uint32_t sb = (uint32_t)__cvta_generic_to_shared(dsm);

    const int z  = blockIdx.z;
    const int z1 = z / nz0;
    const int z0 = z - z1 * nz0;
    const __half* Ab = A + aoffs.o[z1] + (long long)z0 * sA0;
    const __half* Bb = B + boffs.o[z1] + (long long)z0 * sB0;

    const int bm = blockIdx.y * BM;
    const int bn = blockIdx.x * BN;
    const int tid  = threadIdx.x;
    const int lane = tid & 31;
    const int warp = tid >> 5;
    const int warpM = warp >> 2;
    const int warpN = warp & 3;
    const int g = lane >> 2;
    const int c = lane & 3;

    const int lrow  = tid >> 1;
    const int lpart = tid & 1;

    float cfr[4][4][4];
    #pragma unroll
    for (int mt = 0; mt < 4; ++mt)
        #pragma unroll
        for (int nt = 0; nt < 4; ++nt)
            #pragma unroll
            for (int r = 0; r < 4; ++r) cfr[mt][nt][r] = 0.0f;

    auto issue = [&](int s, int k0) {
        uint32_t ad = sb + (uint32_t)((s * STG + lrow * ASTR + lpart * 8) * 4);
        const __half* ap = Ab + (long long)(bm + lrow) * lda + k0 + lpart * 16;
        cpa16(ad, ap); cpa16(ad + 16, ap + 8);
        uint32_t bd = sb + (uint32_t)(((BOFF + s * STG) + lrow * ASTR + lpart * 8) * 4);
        const __half* bp = Bb + (long long)(bn + lrow) * ldb + k0 + lpart * 16;
        cpa16(bd, bp); cpa16(bd + 16, bp + 8);
    };

    auto compute = [&](int s, int k0) {
        const unsigned* Au = dsm + s * STG;
        const unsigned* Bu = dsm + BOFF + s * STG;
        #pragma unroll
        for (int kk = 0; kk < 2; ++kk) {
            unsigned af[4][4], bf[4][2];
            NT16_LOAD_A(Au)
            #pragma unroll
            for (int nt = 0; nt < 4; ++nt) {
                const int n0 = warpN * 32 + nt * 8 + g;
                bf[nt][0] = Bu[n0 * ASTR + kk * 8 + c];
                bf[nt][1] = Bu[n0 * ASTR + kk * 8 + c + 4];
            }
            if (bscale) {
                const int kb = k0 + kk * 16 + 2 * c;
                __half2 s0 = __floats2half2_rn(bscale[kb], bscale[kb + 1]);
                __half2 s1 = __floats2half2_rn(bscale[kb + 8], bscale[kb + 9]);
                #pragma unroll
                for (int nt = 0; nt < 4; ++nt) {
                    bf[nt][0] = hmul2u(bf[nt][0], s0);
                    bf[nt][1] = hmul2u(bf[nt][1], s1);
                }
            }
            NT16_MMA()
        }
    };

    const int T = K / 32;
    issue(0, 0);  CP_COMMIT();
    issue(1, 32); CP_COMMIT();
    issue(2, 64); CP_COMMIT();
    for (int t = 0; t < T; ++t) {
        CP_WAIT2();
        __syncthreads();
        compute(t & 3, t * 32);
        if (t + 3 < T) issue((t + 3) & 3, (t + 3) * 32);
        CP_COMMIT();
    }

    #pragma unroll
    for (int mt = 0; mt < 4; ++mt) {
        const int row = bm + warpM * 64 + mt * 16 + g;
        #pragma unroll
        for (int nt = 0; nt < 4; ++nt) {
            const int col = bn + warpN * 32 + nt * 8 + c * 2;
            #pragma unroll
            for (int half = 0; half < 2; ++half) {
                const int r2 = row + half * 8;
                float v0 = cfr[mt][nt][half * 2 + 0];
                float v1 = cfr[mt][nt][half * 2 + 1];
                if (OUT16) {
                    __half* Ch = (__half*)Cv + coffs.o[z1] + (long long)z0 * sC0;
                    *reinterpret_cast<__half2*>(Ch + (long long)r2 * ldc + col) =
                        __floats2half2_rn(v0, v1);
                } else {
                    float* Cf = (float*)Cv + coffs.o[z1] + (long long)z0 * sC0;
                    float* p = Cf + (long long)r2 * ldc + col;
                    p[0] = v0; p[1] = v1;
                }
            }
        }
    }
}

// ================= fp16 segmented-K NT GEMM (cp.async, fused epilogue) ==============
// act: 1 relu, 2 tanh, 4 gate blend. Output fp16.
__global__ __launch_bounds__(256)
void segk_kernel(int Ktot, HSegArgs sga,
                 const __half* __restrict__ B, int ldb,
                 __half* __restrict__ C, int ldc, long long sC0, ZOffs coffs, int nz0,
                 const float* __restrict__ bias, int act,
                 const __half* __restrict__ e1, long long e1s,
                 const __half* __restrict__ e2, long long e2s)
{
    extern __shared__ unsigned dsm[];
    const uint32_t sb = (uint32_t)__cvta_generic_to_shared(dsm);

    const int z  = blockIdx.z;
    const int z1 = z / nz0;
    const int z0 = z - z1 * nz0;
    __half* Cb = C + coffs.o[z1] + (long long)z0 * sC0;

    const int bm = blockIdx.y * BM;
    const int bn = blockIdx.x * BN;
    const int tid  = threadIdx.x;
    const int lane = tid & 31;
    const int warp = tid >> 5;
    const int warpM = warp >> 2;
    const int warpN = warp & 3;
    const int g = lane >> 2;
    const int c = lane & 3;

    const int lrow  = tid >> 1;
    const int lpart = tid & 1;

    int curseg = -1;
    const __half* Ab = nullptr;

    float cfr[4][4][4];
    #pragma unroll
    for (int mt = 0; mt < 4; ++mt)
        #pragma unroll
        for (int nt = 0; nt < 4; ++nt)
            #pragma unroll
            for (int r = 0; r < 4; ++r) cfr[mt][nt][r] = 0.0f;

    auto issue = [&](int s, int k0) {
        const int sg = k0 >> 10;
        if (sg != curseg) {
            curseg = sg;
            const HSeg& h = sga.segs[sg];
            Ab = h.A + h.c0 + h.c1 * z1 + h.s0 * z0;
        }
        const int kl = k0 & 1023;
        uint32_t ad = sb + (uint32_t)((s * STG + lrow * ASTR + lpart * 8) * 4);
        const __half* ap = Ab + (long long)(bm + lrow) * 1024 + kl + lpart * 16;
        cpa16(ad, ap); cpa16(ad + 16, ap + 8);
        uint32_t bd = sb + (uint32_t)(((BOFF + s * STG) + lrow * ASTR + lpart * 8) * 4);
        const __half* bp = B + (long long)(bn + lrow) * ldb + k0 + lpart * 16;
        cpa16(bd, bp); cpa16(bd + 16, bp + 8);
    };

    auto compute = [&](int s) {
        const unsigned* Au = dsm + s * STG;
        const unsigned* Bu = dsm + BOFF + s * STG;
        #pragma unroll
        for (int kk = 0; kk < 2; ++kk) {
            unsigned af[4][4], bf[4][2];
            NT16_LOAD_A(Au)
            #pragma unroll
            for (int nt = 0; nt < 4; ++nt) {
                const int n0 = warpN * 32 + nt * 8 + g;
                bf[nt][0] = Bu[n0 * ASTR + kk * 8 + c];
                bf[nt][1] = Bu[n0 * ASTR + kk * 8 + c + 4];
            }
            NT16_MMA()
        }
    };

    const int T = Ktot / 32;
    issue(0, 0);  CP_COMMIT();
    issue(1, 32); CP_COMMIT();
    issue(2, 64); CP_COMMIT();
    for (int t = 0; t < T; ++t) {
        CP_WAIT2();
        __syncthreads();
        compute(t & 3);
        if (t + 3 < T) issue((t + 3) & 3, (t + 3) * 32);
        CP_COMMIT();
    }

    #pragma unroll
    for (int mt = 0; mt < 4; ++mt) {
        const int row = bm + warpM * 64 + mt * 16 + g;
        #pragma unroll
        for (int nt = 0; nt < 4; ++nt) {
            const int col = bn + warpN * 32 + nt * 8 + c * 2;
            #pragma unroll
            for (int half = 0; half < 2; ++half) {
                const int r2 = row + half * 8;
                float v0 = cfr[mt][nt][half * 2 + 0];
                float v1 = cfr[mt][nt][half * 2 + 1];
                if (bias) { v0 += bias[col]; v1 += bias[col + 1]; }
                if (act == 1)      { v0 = fmaxf(v0, 0.0f); v1 = fmaxf(v1, 0.0f); }
                else if (act == 2) { v0 = tanhf(v0); v1 = tanhf(v1); }
                else if (act == 4) {
                    const float g0 = 1.0f / (1.0f + expf(-v0));
                    const float g1 = 1.0f / (1.0f + expf(-v1));
                    const __half* pe = e1 + (long long)z0 * e1s + (long long)r2 * ldc + col;
                    const __half* pc = e2 + (long long)z0 * e2s + (long long)r2 * ldc + col;
                    v0 = __half2float(pe[0]) * g0 + __half2float(pc[0]) * (1.0f - g0);
                    v1 = __half2float(pe[1]) * g1 + __half2float(pc[1]) * (1.0f - g1);
                }
                *reinterpret_cast<__half2*>(Cb + (long long)r2 * ldc + col) =
                    __floats2half2_rn(v0, v1);
            }
        }
    }
}

// ================= fp16 NN GEMM (cp.async + ldmatrix.trans), fp16 out ===============
__global__ __launch_bounds__(256)
void nngemm_kernel(int K,
                   const __half* __restrict__ A, int lda, long long sA0, ZOffs aoffs,
                   const __half* __restrict__ B, int ldb, long long sB0, ZOffs boffs,
                   __half* __restrict__ C, int ldc, long long sC0, ZOffs coffs,
                   int nz0)
{
    extern __shared__ unsigned dsm[];
    const uint32_t sb = (uint32_t)__cvta_generic_to_shared(dsm);

    const int z  = blockIdx.z;
    const int z1 = z / nz0;
    const int z0 = z - z1 * nz0;
    const __half* Ab = A + aoffs.o[z1] + (long long)z0 * sA0;
    const __half* Bb = B + boffs.o[z1] + (long long)z0 * sB0;
    __half*       Cb = C + coffs.o[z1] + (long long)z0 * sC0;

    const int bm = blockIdx.y * BM;
    const int bn = blockIdx.x * BN;
    const int tid  = threadIdx.x;
    const int lane = tid & 31;
    const int warp = tid >> 5;
    const int warpM = warp >> 2;
    const int warpN = warp & 3;
    const int g = lane >> 2;
    const int c = lane & 3;

    const int lrow  = tid >> 1;
    const int lpart = tid & 1;
    const int bkr = tid >> 3;           // 0..31
    const int bc8 = tid & 7;            // 16B-pair index

    const uint32_t lane_off = (uint32_t)(lane & 15) * (BNNP * 4) +
                              (uint32_t)(warpN * 32 + ((lane >> 4) << 3)) * 2;

    float cfr[4][4][4];
    #pragma unroll
    for (int mt = 0; mt < 4; ++mt)
        #pragma unroll
        for (int nt = 0; nt < 4; ++nt)
            #pragma unroll
            for (int r = 0; r < 4; ++r) cfr[mt][nt][r] = 0.0f;

    auto issue = [&](int s, int k0) {
        uint32_t ad = sb + (uint32_t)((s * STG + lrow * ASTR + lpart * 8) * 4);
        const __half* ap = Ab + (long long)(bm + lrow) * lda + k0 + lpart * 16;
        cpa16(ad, ap); cpa16(ad + 16, ap + 8);
        uint32_t bd = sb + (uint32_t)(((BOFF + s * NNSTG) + bkr * BNNP + bc8 * 8) * 4);
        const __half* bp = Bb + (long long)(k0 + bkr) * ldb + bn + bc8 * 16;
        cpa16(bd, bp); cpa16(bd + 16, bp + 8);
    };

    auto compute = [&](int s) {
        const unsigned* Au = dsm + s * STG;
        const uint32_t bbuf = sb + (uint32_t)((BOFF + s * NNSTG) * 4) + lane_off;
        #pragma unroll
        for (int kk = 0; kk < 2; ++kk) {
            unsigned af[4][4], bf[4][2];
            NT16_LOAD_A(Au)
            #pragma unroll
            for (int ntp = 0; ntp < 2; ++ntp) {
                const uint32_t addr = bbuf + (uint32_t)(kk * 16) * (BNNP * 4) + (uint32_t)(ntp * 32);
                ldsm_x4_trans(bf[2 * ntp][0], bf[2 * ntp][1], bf[2 * ntp + 1][0], bf[2 * ntp + 1][1], addr);
            }
            NT16_MMA()
        }
    };

    const int T = K / 32;
    issue(0, 0);  CP_COMMIT();
    issue(1, 32); CP_COMMIT();
    issue(2, 64); CP_COMMIT();
    for (int t = 0; t < T; ++t) {
        CP_WAIT2();
        __syncthreads();
        compute(t & 3);
        if (t + 3 < T) issue((t + 3) & 3, (t + 3) * 32);
        CP_COMMIT();
    }

    #pragma unroll
    for (int mt = 0; mt < 4; ++mt) {
        const int row = bm + warpM * 64 + mt * 16 + g;
        #pragma unroll
        for (int nt = 0; nt < 4; ++nt) {
            const int col = bn + warpN * 32 + nt * 8 + c * 2;
            #pragma unroll
            for (int half = 0; half < 2; ++half) {
                const int r2 = row + half * 8;
                *reinterpret_cast<__half2*>(Cb + (long long)r2 * ldc + col) =
                    __floats2half2_rn(cfr[mt][nt][half * 2 + 0], cfr[mt][nt][half * 2 + 1]);
            }
        }
    }
}

// ---------------- fp32 -> fp16 convert ----------------
__global__ void cvt_kernel(const float* __restrict__ src, __half* __restrict__ dst, long long n)
{
    long long i = ((long long)blockIdx.x * 256 + threadIdx.x) * 4;
    if (i < n) {
        float4 v = *reinterpret_cast<const float4*>(src + i);
        __half2 h0 = __floats2half2_rn(v.x, v.y);
        __half2 h1 = __floats2half2_rn(v.z, v.w);
        uint2 u;
        u.x = *reinterpret_cast<unsigned*>(&h0);
        u.y = *reinterpret_cast<unsigned*>(&h1);
        *reinterpret_cast<uint2*>(dst + i) = u;
    }
}

// ---------------- elementwise mul+sub (half2) ----------------
__global__ void ewpair_kernel(const __half* __restrict__ X, ZOffs xo, long long xs0,
                              const __half* __restrict__ Y,
                              __half* __restrict__ M, __half* __restrict__ Sb,
                              int nPer, int nz0)
{
    const int z = blockIdx.y;
    const int z1 = z / nz0, z0 = z - z1 * nz0;
    const long long t = ((long long)blockIdx.x * 256 + threadIdx.x) * 2;
    const __half2 x = *reinterpret_cast<const __half2*>(X + xo.o[z1] + (long long)z0 * xs0 + t);
    const __half2 y = *reinterpret_cast<const __half2*>(Y + (long long)z * nPer + t);
    *reinterpret_cast<__half2*>(M + (long long)z * nPer + t) = __hmul2(x, y);
    *reinterpret_cast<__half2*>(Sb + (long long)z * nPer + t) = __hsub2(x, y);
}

// ---------------- batched rowdot (half X, fp32 w) ----------------
__global__ void rowdot_kernel(const __half* __restrict__ X, ZOffs offs, int nz0, long long s0,
                              int ld, const float* __restrict__ w, float* __restrict__ out,
                              int rows, int Kd)
{
    __shared__ float sm[32];
    const int r = blockIdx.x, z = blockIdx.y;
    const int z1 = z / nz0, z0 = z - z1 * nz0;
    const __half* x = X + offs.o[z1] + (long long)z0 * s0 + (long long)r * ld;
    float s = 0.0f;
    for (int k = threadIdx.x; k < Kd; k += 256) s += __half2float(x[k]) * w[k];
    s = blockReduceSum(s, sm);
    if (threadIdx.x == 0) out[(long long)z * rows + r] = s;
}

// ---------------- row softmax: fp32 S in, fp16 P out ----------------
__global__ void softmax_row_kernel(const float* __restrict__ S, __half* __restrict__ P,
                                   int ldS, long long strideS,
                                   const float* __restrict__ kl, ZOffs klo, long long kls0,
                                   int nz0, int Lk)
{
    __shared__ float sm[32];
    const int q = blockIdx.x, z = blockIdx.y;
    const int z1 = z / nz0, z0 = z - z1 * nz0;
    const float* row = S + (long long)z * strideS + (long long)q * ldS;
    __half* prow = P + (long long)z * strideS + (long long)q * ldS;
    const float* klb = kl + klo.o[z1] + (long long)z0 * kls0;

    float v[3];
    int n = 0;
    float m = -3.4e38f;
    for (int k = threadIdx.x; k < Lk; k += 256) {
        float x = row[k] + klb[k];
        v[n++] = x;
        m = fmaxf(m, x);
    }
    m = blockReduceMax(m, sm);
    float s = 0.0f;
    for (int t = 0; t < n; ++t) { v[t] = expf(v[t] - m); s += v[t]; }
    s = blockReduceSum(s, sm);
    const float inv = 1.0f / s;
    n = 0;
    for (int k = threadIdx.x; k < Lk; k += 256) prow[k] = __float2half(v[n++] * inv);
}

// ---------------- column softmax (doc): fp32 S in, fp16 kq out ----------------
__global__ void softmax_col_kernel(const float* __restrict__ S, __half* __restrict__ kq,
                                   const float* __restrict__ ql)
{
    const int x = threadIdx.x & 31;
    const int y = threadIdx.x >> 5;
    const int col = blockIdx.x * 32 + x;
    const int z = blockIdx.y;
    const float* Sb = S + (long long)z * (LO * LDOC);
    const float* qlb = ql + (long long)z * LO;

    float vals[LO / 8];
    float m = -3.4e38f;
    #pragma unroll 4
    for (int it = 0; it < LO / 8; ++it) {
        const int r = it * 8 + y;
        float v = qlb[r] + Sb[(long long)r * LDOC + col];
        vals[it] = v;
        m = fmaxf(m, v);
    }
    __shared__ float red[8][32];
    red[y][x] = m;
    __syncthreads();
    if (y == 0) {
        float mm = red[0][x];
        #pragma unroll
        for (int t = 1; t < 8; ++t) mm = fmaxf(mm, red[t][x]);
        red[0][x] = mm;
    }
    __syncthreads();
    m = red[0][x];
    __syncthreads();

    float s = 0.0f;
    #pragma unroll 4
    for (int it = 0; it < LO / 8; ++it) { vals[it] = expf(vals[it] - m); s += vals[it]; }
    red[y][x] = s;
    __syncthreads();
    if (y == 0) {
        float ss = 0.0f;
        #pragma unroll
        for (int t = 0; t < 8; ++t) ss += red[t][x];
        red[0][x] = ss;
    }
    __syncthreads();
    const float inv = 1.0f / red[0][x];

    __half* kqb = kq + (long long)z * (LO * LDOC);
    #pragma unroll 4
    for (int it = 0; it < LO / 8; ++it)
        kqb[(long long)(it * 8 + y) * LDOC + col] = __float2half(vals[it] * inv);
}

// ---------------- final max over positions (half in, fp32 out) ----------------
__global__ void maxreduce_kernel(const __half* __restrict__ f, float* __restrict__ out)
{
    const int h = blockIdx.x * 256 + threadIdx.x;
    const int b = blockIdx.y;
    float m = -3.4e38f;
    const __half* base = f + (long long)b * LO * HD + h;
    #pragma unroll 8
    for (int r = 0; r < LO; ++r) m = fmaxf(m, __half2float(base[(long long)r * HD]));
    out[(long long)b * HD + h] = m;
}

// ---------------- host ----------------
static ZOffs zzero() { ZOffs z; for (int i = 0; i < 12; ++i) z.o[i] = 0; return z; }

extern "C" void kernel_launch(void* const* d_in, const int* in_sizes, int n_in,
                              void* d_out, int out_size)
{
    cudaFuncSetAttribute(tgemm_kernel<0>, cudaFuncAttributeMaxDynamicSharedMemorySize, NT_SMEM);
    cudaFuncSetAttribute(tgemm_kernel<1>, cudaFuncAttributeMaxDynamicSharedMemorySize, NT_SMEM);
    cudaFuncSetAttribute(segk_kernel, cudaFuncAttributeMaxDynamicSharedMemorySize, NT_SMEM);
    cudaFuncSetAttribute(nngemm_kernel, cudaFuncAttributeMaxDynamicSharedMemorySize, NN_SMEM);

    const float* last   = (const float*)d_in[4];
    const float* ow2    = (const float*)d_in[6];
    const float* ow3    = (const float*)d_in[7];
    const float* dw1    = (const float*)d_in[8];
    const float* dw2    = (const float*)d_in[9];
    const float* dw3    = (const float*)d_in[10];
    const float* sw2    = (const float*)d_in[12];
    const float* sw3    = (const float*)d_in[13];
    const float* comp_w = (const float*)d_in[14];
    const float* comp_b = (const float*)d_in[15];
    const float* gate_w = (const float*)d_in[16];
    const float* gate_b = (const float*)d_in[17];
    const float* attn_w = (const float*)d_in[18];
    const float* attn_b = (const float*)d_in[19];
    const float* self_w = (const float*)d_in[20];
    const float* self_b = (const float*)d_in[21];

    float *S_, *kl_, *ql_;
    __half *hlast, *hatt, *hmul, *hsub, *hP, *hkq, *hcow, *hcorr, *hopt, *ha, *hco, *hfus, *hsa, *hfm, *hfs;
    __half *hcompw, *hgatew, *hattnw, *hselfw;
    cudaGetSymbolAddress((void**)&S_,  g_S);
    cudaGetSymbolAddress((void**)&kl_, g_kl);
    cudaGetSymbolAddress((void**)&ql_, g_ql);
    cudaGetSymbolAddress((void**)&hlast, h_last);
    cudaGetSymbolAddress((void**)&hatt,  h_att);
    cudaGetSymbolAddress((void**)&hmul,  h_mul);
    cudaGetSymbolAddress((void**)&hsub,  h_sub);
    cudaGetSymbolAddress((void**)&hP,    h_P);
    cudaGetSymbolAddress((void**)&hkq,   h_kq);
    cudaGetSymbolAddress((void**)&hcow,  h_cow);
    cudaGetSymbolAddress((void**)&hcorr, h_corr);
    cudaGetSymbolAddress((void**)&hopt,  h_opt);
    cudaGetSymbolAddress((void**)&ha,    h_a);
    cudaGetSymbolAddress((void**)&hco,   h_co);
    cudaGetSymbolAddress((void**)&hfus,  h_fus);
    cudaGetSymbolAddress((void**)&hsa,   h_sa);
    cudaGetSymbolAddress((void**)&hfm,   h_fm);
    cudaGetSymbolAddress((void**)&hfs,   h_fs);
    cudaGetSymbolAddress((void**)&hcompw, h_compw);
    cudaGetSymbolAddress((void**)&hgatew, h_gatew);
    cudaGetSymbolAddress((void**)&hattnw, h_attnw);
    cudaGetSymbolAddress((void**)&hselfw, h_selfw);

    const long long sSeq = (long long)SEQ * HD;
    const long long sQ   = 4LL * SEQ * HD;
    const long long LoH  = (long long)LO * HD;
    const int nPer = LO * HD;

    // ===== input conversions =====
    cvt_kernel<<<(NBAT * (long long)SEQ * HD) / 1024, 256>>>(last, hlast, (long long)NBAT * SEQ * HD);
    cvt_kernel<<<(7LL * HD * HD) / 1024, 256>>>(comp_w, hcompw, 7LL * HD * HD);
    cvt_kernel<<<(2LL * HD * HD) / 1024, 256>>>(gate_w, hgatew, 2LL * HD * HD);
    cvt_kernel<<<(3LL * HD * HD) / 1024, 256>>>(attn_w, hattnw, 3LL * HD * HD);
    cvt_kernel<<<(4LL * HD * HD) / 1024, 256>>>(self_w, hselfw, 4LL * HD * HD);

    long long curoff[NL], kvoff[12];
    int jv[12];
    for (int i = 0; i < NL; ++i) curoff[i] = ((long long)i * SEQ + LDOC) * HD;
    for (int i = 0, p = 0; i < NL; ++i)
        for (int j = 0; j < NL; ++j) {
            if (j == i) continue;
            kvoff[p] = ((long long)j * SEQ + LDOC) * HD;
            jv[p] = j;
            ++p;
        }

    // ===== Stage A: 12 pair attentions =====
    {
        ZOffs lblo = zzero();
        for (int j = 0; j < NL; ++j) lblo.o[j] = ((long long)j * SEQ + LDOC) * HD;
        rowdot_kernel<<<dim3(LO, NL * NBZ), 256>>>(hlast, lblo, NBZ, sQ, HD, ow2, kl_, LO, HD);

        ZOffs kvo = zzero(), ao = zzero(), co = zzero();
        for (int p = 0; p < 12; ++p) {
            kvo.o[p] = kvoff[p];
            ao.o[p] = curoff[p / 3];
            co.o[p] = (long long)p * NBZ * LO * LO;
        }
        tgemm_kernel<0><<<dim3(LO / BN, LO / BM, 96), 256, NT_SMEM>>>(
            HD, hlast, HD, sQ, ao, hlast, HD, sQ, kvo,
            S_, LO, (long long)LO * LO, co, NBZ, ow3);

        ZOffs klo = zzero();
        for (int p = 0; p < 12; ++p) klo.o[p] = (long long)jv[p] * NBZ * LO;
        softmax_row_kernel<<<dim3(LO, 96), 256>>>(S_, hP, LO, (long long)LO * LO, kl_, klo, LO, NBZ, LO);

        ZOffs ato = zzero();
        for (int p = 0; p < 12; ++p) ato.o[p] = (long long)p * NBZ * LoH;
        nngemm_kernel<<<dim3(HD / BN, LO / BM, 96), 256, NN_SMEM>>>(
            LO, hP, LO, (long long)LO * LO, co, hlast, HD, sQ, kvo,
            hatt, HD, LoH, ato, NBZ);

        // products: h_mul = cur*att, h_sub = cur-att
        ZOffs xo = zzero();
        for (int p = 0; p < 12; ++p) xo.o[p] = curoff[p / 3];
        ewpair_kernel<<<dim3(nPer / 512, 96), 256>>>(hlast, xo, sQ, hatt, hmul, hsub, nPer, NBZ);
    }

    // ===== comp: segmented GEMM K=7168 =====
    {
        HSegArgs sga = {};
        sga.segs[0] = {hlast, (long long)LDOC * HD, (long long)SEQ * HD, sQ};
        for (int m = 0; m < 3; ++m) {
            sga.segs[1 + 2 * m] = {hmul, (long long)m * NBZ * LoH, 3LL * NBZ * LoH, LoH};
            sga.segs[2 + 2 * m] = {hsub, (long long)m * NBZ * LoH, 3LL * NBZ * LoH, LoH};
        }
        sga.nseg = 7;
        ZOffs co = zzero();
        for (int i = 0; i < NL; ++i) co.o[i] = (long long)i * LoH;
        segk_kernel<<<dim3(HD / BN, LO / BM, 32), 256, NT_SMEM>>>(
            7 * HD, sga, hcompw, 7 * HD,
            hcorr, HD, 4 * LoH, co, NBZ,
            comp_b, 2, nullptr, 0, nullptr, 0);
    }

    // ===== Stage B: gate + blend -> opt =====
    {
        HSegArgs sga = {};
        sga.segs[0] = {hlast, (long long)LDOC * HD, 0, sSeq};
        sga.segs[1] = {hcorr, 0, 0, LoH};
        sga.nseg = 2;
        segk_kernel<<<dim3(HD / BN, LO / BM, 32), 256, NT_SMEM>>>(
            2 * HD, sga, hgatew, 2 * HD,
            hopt, HD, LoH, zzero(), NBAT,
            gate_b, 4, hlast + (long long)LDOC * HD, sSeq, hcorr, LoH);
    }

    // ===== Stage C: doc attention =====
    {
        ZOffs z0o = zzero();
        rowdot_kernel<<<dim3(LO, NBAT), 256>>>(hopt, z0o, NBAT, LoH, HD, dw1, ql_, LO, HD);
        rowdot_kernel<<<dim3(LDOC, NBAT), 256>>>(hlast, z0o, NBAT, sSeq, HD, dw2, kl_, LDOC, HD);

        tgemm_kernel<0><<<dim3(LDOC / BN, LO / BM, 32), 256, NT_SMEM>>>(
            HD, hopt, HD, LoH, zzero(), hlast, HD, sSeq, zzero(),
            S_, LDOC, (long long)LO * LDOC, zzero(), NBAT, dw3);

        softmax_col_kernel<<<dim3(LDOC / 32, NBAT), 256>>>(S_, hkq, ql_);
        softmax_row_kernel<<<dim3(LO, NBAT), 256>>>(S_, hP, LDOC, (long long)LO * LDOC, kl_, zzero(), LDOC, NBAT, LDOC);

        nngemm_kernel<<<dim3(HD / BN, LO / BM, 32), 256, NN_SMEM>>>(
            LDOC, hP, LDOC, (long long)LO * LDOC, zzero(), hlast, HD, sSeq, zzero(),
            ha, HD, LoH, zzero(), NBAT);

        tgemm_kernel<1><<<dim3(LO / BN, LO / BM, 32), 256, NT_SMEM>>>(
            LDOC, hP, LDOC, (long long)LO * LDOC, zzero(), hkq, LDOC, (long long)LO * LDOC, zzero(),
            hcow, LO, (long long)LO * LO, zzero(), NBAT, nullptr);

        nngemm_kernel<<<dim3(HD / BN, LO / BM, 32), 256, NN_SMEM>>>(
            LO, hcow, LO, (long long)LO * LO, zzero(), hopt, HD, LoH, zzero(),
            hco, HD, LoH, zzero(), NBAT);
    }

    // ===== Stage D: fusion =====
    {
        HSegArgs sga = {};
        sga.segs[0] = {hopt, 0, 0, LoH};
        sga.segs[1] = {ha,   0, 0, LoH};
        sga.segs[2] = {hco,  0, 0, LoH};
        sga.nseg = 3;
        segk_kernel<<<dim3(HD / BN, LO / BM, 32), 256, NT_SMEM>>>(
            3 * HD, sga, hattnw, 3 * HD,
            hfus, HD, LoH, zzero(), NBAT,
            attn_b, 1, nullptr, 0, nullptr, 0);
    }

    // ===== Stage E: self attention =====
    {
        ZOffs z0o = zzero();
        rowdot_kernel<<<dim3(LO, NBAT), 256>>>(hfus, z0o, NBAT, LoH, HD, sw2, kl_, LO, HD);

        tgemm_kernel<0><<<dim3(LO / BN, LO / BM, 32), 256, NT_SMEM>>>(
            HD, hfus, HD, LoH, zzero(), hfus, HD, LoH, zzero(),
            S_, LO, (long long)LO * LO, zzero(), NBAT, sw3);

        softmax_row_kernel<<<dim3(LO, NBAT), 256>>>(S_, hP, LO, (long long)LO * LO, kl_, zzero(), LO, NBAT, LO);

        nngemm_kernel<<<dim3(HD / BN, LO / BM, 32), 256, NN_SMEM>>>(
            LO, hP, LO, (long long)LO * LO, zzero(), hfus, HD, LoH, zzero(),
            hsa, HD, LoH, zzero(), NBAT);
    }

    // ===== Stage F: fusion2 =====
    {
        ewpair_kernel<<<dim3(nPer / 512, NBAT), 256>>>(hfus, zzero(), LoH, hsa, hfm, hfs, nPer, NBAT);

        HSegArgs sga = {};
        sga.segs[0] = {hfus, 0, 0, LoH};
        sga.segs[1] = {hsa,  0, 0, LoH};
        sga.segs[2] = {hfm,  0, 0, LoH};
        sga.segs[3] = {hfs,  0, 0, LoH};
        sga.nseg = 4;
        segk_kernel<<<dim3(HD / BN, LO / BM, 32), 256, NT_SMEM>>>(
            4 * HD, sga, hselfw, 4 * HD,
            hcorr, HD, LoH, zzero(), NBAT,
            self_b, 1, nullptr, 0, nullptr, 0);
    }

    // ===== Stage G =====
    maxreduce_kernel<<<dim3(HD / 256, NBAT), 256>>>(hcorr, (float*)d_out);
}